// round 2
// baseline (speedup 1.0000x reference)
#include <cuda_runtime.h>
#include <math_constants.h>

#define N      8192
#define D      128
#define LALPHA 0.2f
#define THR    1e-4f
#define SPLIT  8
#define BM     128
#define BK     32
#define JR     (N / SPLIT)   // 1024 j's per split

// ---------------- scratch (static device globals; no allocation) ------------
__device__ float g_h[N * D];          // 4 MB   h = X @ W
__device__ float g_src[N];            // h . a_src
__device__ float g_dst[N];            // h . a_dst
__device__ int   g_nz[N];             // rowsum(h) != 0
__device__ float g_m[N];              // row max of masked e (or +INF if row inactive)
__device__ float g_s[N];              // row softmax denom (or 1 if inactive)
__device__ float g_L[N];              // valid count as float (or 0 if inactive)
__device__ float g_part[SPLIT][N * D]; // 32 MB  split-K partials

// ---------------- K1: h = X @ W + per-row scalars ---------------------------
__global__ void k_h(const float* __restrict__ x,
                    const float* __restrict__ W,
                    const float* __restrict__ a) {
    int i = blockIdx.x;
    int k = threadIdx.x;   // 0..127

    __shared__ float xs[D];
    __shared__ float red[D];

    xs[k] = x[i * D + k];
    __syncthreads();

    float acc = 0.f;
#pragma unroll 16
    for (int c = 0; c < D; ++c)
        acc = fmaf(xs[c], W[c * D + k], acc);

    g_h[i * D + k] = acc;

    float vals[3];
    vals[0] = acc;              // rowsum
    vals[1] = acc * a[k];       // src contribution
    vals[2] = acc * a[D + k];   // dst contribution

#pragma unroll
    for (int v = 0; v < 3; ++v) {
        red[k] = vals[v];
        __syncthreads();
        for (int st = 64; st > 0; st >>= 1) {
            if (k < st) red[k] += red[k + st];
            __syncthreads();
        }
        if (k == 0) {
            if (v == 0)      g_nz[i]  = (red[0] != 0.0f) ? 1 : 0;
            else if (v == 1) g_src[i] = red[0];
            else             g_dst[i] = red[0];
        }
        __syncthreads();
    }
}

// ---------------- K2: per-row softmax stats (m, s, L, active flag) ----------
__global__ void k_stats(const int* __restrict__ adj) {
    int i   = blockIdx.x;
    int tid = threadIdx.x;   // 0..255

    const int4* arow = (const int4*)(adj + (long)i * N);
    float si = g_src[i];

    // pass 1: max + count over valid
    float m_t = -CUDART_INF_F;
    int   cnt = 0;
#pragma unroll
    for (int t = 0; t < 8; ++t) {
        int  q  = tid + t * 256;     // 0..2047
        int4 av = arow[q];
        int  j0 = 4 * q;
        int  aa[4] = {av.x, av.y, av.z, av.w};
#pragma unroll
        for (int u = 0; u < 4; ++u) {
            if (aa[u] > 0 && g_nz[j0 + u]) {
                float e = si + g_dst[j0 + u];
                e = (e > 0.f) ? e : LALPHA * e;
                m_t = fmaxf(m_t, e);
                cnt++;
            }
        }
    }

    __shared__ float sm[256];
    __shared__ int   sc[256];
    sm[tid] = m_t; sc[tid] = cnt;
    __syncthreads();
    for (int st = 128; st > 0; st >>= 1) {
        if (tid < st) {
            sm[tid] = fmaxf(sm[tid], sm[tid + st]);
            sc[tid] += sc[tid + st];
        }
        __syncthreads();
    }
    float m = sm[0];
    int   L = sc[0];
    __syncthreads();

    // pass 2: sum of exp(e - m) over valid (adj row hits L1/L2)
    float s_t = 0.f;
#pragma unroll
    for (int t = 0; t < 8; ++t) {
        int  q  = tid + t * 256;
        int4 av = arow[q];
        int  j0 = 4 * q;
        int  aa[4] = {av.x, av.y, av.z, av.w};
#pragma unroll
        for (int u = 0; u < 4; ++u) {
            if (aa[u] > 0 && g_nz[j0 + u]) {
                float e = si + g_dst[j0 + u];
                e = (e > 0.f) ? e : LALPHA * e;
                s_t += __expf(e - m);
            }
        }
    }
    sm[tid] = s_t;
    __syncthreads();
    for (int st = 128; st > 0; st >>= 1) {
        if (tid < st) sm[tid] += sm[tid + st];
        __syncthreads();
    }

    if (tid == 0) {
        float s = sm[0];
        // top = max(att) = 1/s when any valid; row active iff top > THR
        bool active = (L > 0) && (1.0f / s > THR);
        if (active) {
            g_m[i] = m; g_s[i] = s; g_L[i] = (float)L;
        } else {
            // exp(e - INF) = 0 -> att = 0 -> weight = 0 uniformly, no NaN
            g_m[i] = CUDART_INF_F; g_s[i] = 1.f; g_L[i] = 0.f;
        }
    }
}

// ---------------- K3: h_prime partials = attention @ h (split-K) ------------
__global__ void __launch_bounds__(256, 2)
k_agg(const int* __restrict__ adj) {
    int ib    = blockIdx.x * BM;
    int split = blockIdx.y;
    int tid   = threadIdx.x;

    __shared__ float h_s[BK][D];          // 16 KB
    __shared__ float w_s[BM][BK + 1];     // pad=33 -> conflict-free
    __shared__ float srcs[BM], ms[BM], ssv[BM], Ls[BM];

    if (tid < BM) {
        int r = ib + tid;
        srcs[tid] = g_src[r];
        ms[tid]   = g_m[r];
        ssv[tid]  = g_s[r];
        Ls[tid]   = g_L[r];
    }
    __syncthreads();

    float acc[8][8];
#pragma unroll
    for (int r = 0; r < 8; ++r)
#pragma unroll
        for (int c = 0; c < 8; ++c) acc[r][c] = 0.f;

    int tc = tid & 15, tr = tid >> 4;
    int i0 = tr * 8, k0 = tc * 8;
    int jstart = split * JR;

    for (int t = 0; t < JR / BK; ++t) {
        int jb = jstart + t * BK;

        // stage h tile [BK][D]
#pragma unroll
        for (int q = 0; q < 4; ++q) {
            int idx = tid + q * 256;
            int r   = idx >> 5, c4 = idx & 31;
            ((float4*)h_s[r])[c4] = ((const float4*)(g_h + (jb + r) * D))[c4];
        }

        // generate weight tile [BM][BK]
#pragma unroll
        for (int q = 0; q < 16; ++q) {
            int idx = tid + q * 256;
            int i   = idx >> 5, j = idx & 31;
            int jg  = jb + j;
            int av  = adj[(long)(ib + i) * N + jg];
            float e = srcs[i] + g_dst[jg];
            e = (e > 0.f) ? e : LALPHA * e;
            float att = __expf(e - ms[i]) / ssv[i];
            float w   = (av > 0 && g_nz[jg] && att >= THR) ? att * Ls[i] : 0.f;
            w_s[i][j] = w;
        }
        __syncthreads();

        // accumulate 8x8 micro-tile over BK j's
#pragma unroll 2
        for (int j = 0; j < BK; ++j) {
            float4 h0 = *(const float4*)&h_s[j][k0];
            float4 h1 = *(const float4*)&h_s[j][k0 + 4];
            float hv[8] = {h0.x, h0.y, h0.z, h0.w, h1.x, h1.y, h1.z, h1.w};
            float wv[8];
#pragma unroll
            for (int r = 0; r < 8; ++r) wv[r] = w_s[i0 + r][j];
#pragma unroll
            for (int r = 0; r < 8; ++r)
#pragma unroll
                for (int c = 0; c < 8; ++c)
                    acc[r][c] = fmaf(wv[r], hv[c], acc[r][c]);
        }
        __syncthreads();
    }

    // write split partial
#pragma unroll
    for (int r = 0; r < 8; ++r) {
        int row = ib + i0 + r;
        float* p = &g_part[split][row * D + k0];
        *(float4*)(p)     = make_float4(acc[r][0], acc[r][1], acc[r][2], acc[r][3]);
        *(float4*)(p + 4) = make_float4(acc[r][4], acc[r][5], acc[r][6], acc[r][7]);
    }
}

// ---------------- K4: combine partials + residual + ELU ---------------------
__global__ void k_out(float* __restrict__ out) {
    int g = blockIdx.x * blockDim.x + threadIdx.x;
    float v = g_h[g];
#pragma unroll
    for (int s = 0; s < SPLIT; ++s) v += g_part[s][g];
    out[g] = (v > 0.f) ? v : expm1f(v);
}

// ---------------- launch ----------------------------------------------------
extern "C" void kernel_launch(void* const* d_in, const int* in_sizes, int n_in,
                              void* d_out, int out_size) {
    (void)in_sizes; (void)n_in; (void)out_size;
    const float* x   = (const float*)d_in[0];
    const float* W   = (const float*)d_in[1];
    const float* a   = (const float*)d_in[2];
    const int*   adj = (const int*)d_in[3];
    float*       out = (float*)d_out;

    k_h    <<<N, 128>>>(x, W, a);
    k_stats<<<N, 256>>>(adj);
    k_agg  <<<dim3(N / BM, SPLIT), 256>>>(adj);
    k_out  <<<(N * D) / 256, 256>>>(out);
}

// round 3
// speedup vs baseline: 1.7819x; 1.7819x over previous
#include <cuda_runtime.h>
#include <math_constants.h>

#define N      8192
#define D      128
#define THR    1e-4f
#define SPLIT  4
#define BM     128
#define BK     32
#define JR     (N / SPLIT)   // 2048 j's per split
#define SROWS  8             // rows per k_stats block

// ---------------- scratch (static device globals; no allocation) ------------
__device__ float    g_h[N * D];             // 4 MB   h = X @ W
__device__ float    g_src[N];               // h . a_src
__device__ float    g_dst[N];               // h . a_dst
__device__ float    g_Bz[N];                // nz_j ? exp(dst_j)      : 0
__device__ float    g_Cz[N];                // nz_j ? exp(0.2*dst_j)  : 0
__device__ float4   g_rowc[N];              // {fa, fb, Ta, Tb} per row
__device__ unsigned g_mask[(size_t)N * N / 32];   // 8 MB adjacency bitmask
__device__ float    g_part[SPLIT][N * D];   // 16 MB split-K partials

__device__ __forceinline__ void ffma2(unsigned long long& d,
                                      unsigned long long a,
                                      unsigned long long b) {
    asm("fma.rn.f32x2 %0, %1, %2, %0;" : "+l"(d) : "l"(a), "l"(b));
}

// ---------------- K1: h = X @ W + per-node scalars --------------------------
__global__ void k_h(const float* __restrict__ x,
                    const float* __restrict__ W,
                    const float* __restrict__ a) {
    int i = blockIdx.x;
    int k = threadIdx.x;   // 0..127

    __shared__ float xs[D];
    __shared__ float red[D];
    __shared__ float res[3];

    xs[k] = x[i * D + k];
    __syncthreads();

    float acc = 0.f;
#pragma unroll 16
    for (int c = 0; c < D; ++c)
        acc = fmaf(xs[c], W[c * D + k], acc);

    g_h[i * D + k] = acc;

    float vals[3];
    vals[0] = acc;              // rowsum
    vals[1] = acc * a[k];       // src contribution
    vals[2] = acc * a[D + k];   // dst contribution

#pragma unroll
    for (int v = 0; v < 3; ++v) {
        red[k] = vals[v];
        __syncthreads();
        for (int st = 64; st > 0; st >>= 1) {
            if (k < st) red[k] += red[k + st];
            __syncthreads();
        }
        if (k == 0) res[v] = red[0];
        __syncthreads();
    }

    if (k == 0) {
        float rs = res[0], s = res[1], d = res[2];
        bool  nz = (rs != 0.0f);
        g_src[i] = s;
        g_dst[i] = d;
        g_Bz[i]  = nz ? __expf(d)        : 0.f;
        g_Cz[i]  = nz ? __expf(0.2f * d) : 0.f;
    }
}

// ---------------- K2: single-pass softmax stats + bitmask -------------------
// block = SROWS rows; warp w owns row (block0 + w). One adj pass total.
__global__ void k_stats(const int* __restrict__ adj) {
    int row  = blockIdx.x * SROWS + (threadIdx.x >> 5);
    int lane = threadIdx.x & 31;

    __shared__ float sd[512], sb[512], sc[512];

    float src = g_src[row];
    float ea  = __expf(src);
    float eb  = __expf(0.2f * src);

    float s = 0.f, vm = 0.f;
    int   cnt = 0;
    const int* arow = adj + (size_t)row * N;

    for (int ch = 0; ch < N / 512; ++ch) {
        int jb = ch * 512;
        __syncthreads();
        for (int q = threadIdx.x; q < 512; q += 256) {
            sd[q] = g_dst[jb + q];
            sb[q] = g_Bz[jb + q];
            sc[q] = g_Cz[jb + q];
        }
        __syncthreads();
#pragma unroll 4
        for (int st = 0; st < 16; ++st) {
            int j = jb + st * 32 + lane;
            int a = arow[j];
            bool bit = (a > 0);
            unsigned bal = __ballot_sync(0xffffffffu, bit);
            if (lane == 0)
                g_mask[(size_t)row * (N / 32) + (j >> 5)] = bal;

            int   q   = st * 32 + lane;
            float dv  = sd[q];
            bool  pos = (src + dv) > 0.f;
            float b   = pos ? sb[q] : sc[q];
            float f   = pos ? ea    : eb;
            float v   = bit ? b * f : 0.f;
            s  += v;
            vm  = fmaxf(vm, v);
            cnt += (bit && b > 0.f) ? 1 : 0;
        }
    }

    // warp reduce (row is warp-private)
#pragma unroll
    for (int o = 16; o > 0; o >>= 1) {
        s   += __shfl_xor_sync(0xffffffffu, s, o);
        vm   = fmaxf(vm, __shfl_xor_sync(0xffffffffu, vm, o));
        cnt += __shfl_xor_sync(0xffffffffu, cnt, o);
    }

    if (lane == 0) {
        // top = vm/s ; active iff top > THR (strict) and any valid
        bool active = (vm > THR * s);
        float fa = 0.f, fb = 0.f, Ta = CUDART_INF_F, Tb = CUDART_INF_F;
        if (active) {
            float inv = 1.0f / s;
            float L   = (float)cnt;
            fa = ea * inv * L;
            fb = eb * inv * L;
            Ta = THR * s / ea;   // b >= Ta  <=>  att >= THR  (pos branch)
            Tb = THR * s / eb;
        }
        g_rowc[row] = make_float4(fa, fb, Ta, Tb);
    }
}

// ---------------- K3: h_prime partials = attention @ h (FFMA2, split-K) -----
__global__ void __launch_bounds__(256, 2) k_agg() {
    int ib    = blockIdx.x * BM;
    int split = blockIdx.y;
    int tid   = threadIdx.x;

    __shared__ __align__(16) float h_s[BK][D];   // 16 KB
    __shared__ float  w_s[BM][BK + 1];           // 16.5 KB, conflict-free
    __shared__ float  srcs[BM];
    __shared__ float4 rcs[BM];

    if (tid < BM) {
        srcs[tid] = g_src[ib + tid];
        rcs[tid]  = g_rowc[ib + tid];
    }
    __syncthreads();

    int iown  = tid >> 1;          // row this thread generates weights for
    int jhalf = (tid & 1) << 4;    // which 16-j half
    float  my_src = srcs[iown];
    float4 rc     = rcs[iown];
    const unsigned* mrow = g_mask + (size_t)(ib + iown) * (N / 32);

    unsigned long long acc[8][4];
#pragma unroll
    for (int r = 0; r < 8; ++r)
#pragma unroll
        for (int c = 0; c < 4; ++c) acc[r][c] = 0ull;

    int tc = tid & 15, tr = tid >> 4;
    int i0 = tr * 8, k0 = tc * 8;
    int jstart = split * JR;

    for (int t = 0; t < JR / BK; ++t) {
        int jb = jstart + t * BK;
        __syncthreads();   // previous tile's reads complete

        // stage h tile [BK][D]
#pragma unroll
        for (int q = 0; q < 4; ++q) {
            int idx = tid + q * 256;
            int r = idx >> 5, c4 = idx & 31;
            ((float4*)h_s[r])[c4] =
                ((const float4*)(g_h + (size_t)(jb + r) * D))[c4];
        }

        // generate weight tile: thread -> (iown, 16 j's)
        unsigned mw = mrow[jb >> 5];
        const float4* dv4 = (const float4*)(g_dst + jb + jhalf);
        const float4* bz4 = (const float4*)(g_Bz  + jb + jhalf);
        const float4* cz4 = (const float4*)(g_Cz  + jb + jhalf);
#pragma unroll
        for (int e4 = 0; e4 < 4; ++e4) {
            float4 dv = __ldg(&dv4[e4]);
            float4 bz = __ldg(&bz4[e4]);
            float4 cz = __ldg(&cz4[e4]);
            float dva[4] = {dv.x, dv.y, dv.z, dv.w};
            float bza[4] = {bz.x, bz.y, bz.z, bz.w};
            float cza[4] = {cz.x, cz.y, cz.z, cz.w};
#pragma unroll
            for (int u = 0; u < 4; ++u) {
                int   j   = jhalf + e4 * 4 + u;
                bool  pos = (my_src + dva[u]) > 0.f;
                float b   = pos ? bza[u] : cza[u];
                float T   = pos ? rc.z   : rc.w;
                float f   = pos ? rc.x   : rc.y;
                bool  ok  = (b >= T) && ((mw >> j) & 1u);
                w_s[iown][j] = ok ? b * f : 0.f;
            }
        }
        __syncthreads();

        // 8x8 micro-tile accumulation via packed fp32x2 FMA
#pragma unroll
        for (int j = 0; j < BK; ++j) {
            ulonglong2 ha = *(const ulonglong2*)&h_s[j][k0];
            ulonglong2 hb = *(const ulonglong2*)&h_s[j][k0 + 4];
#pragma unroll
            for (int r = 0; r < 8; ++r) {
                unsigned long long wr;
                asm("mov.b64 %0, {%1, %1};"
                    : "=l"(wr) : "r"(__float_as_uint(w_s[i0 + r][j])));
                ffma2(acc[r][0], wr, ha.x);
                ffma2(acc[r][1], wr, ha.y);
                ffma2(acc[r][2], wr, hb.x);
                ffma2(acc[r][3], wr, hb.y);
            }
        }
    }

    // write split partial
#pragma unroll
    for (int r = 0; r < 8; ++r) {
        float* p = &g_part[split][(size_t)(ib + i0 + r) * D + k0];
        float2 v0 = *(float2*)&acc[r][0];
        float2 v1 = *(float2*)&acc[r][1];
        float2 v2 = *(float2*)&acc[r][2];
        float2 v3 = *(float2*)&acc[r][3];
        *(float4*)(p)     = make_float4(v0.x, v0.y, v1.x, v1.y);
        *(float4*)(p + 4) = make_float4(v2.x, v2.y, v3.x, v3.y);
    }
}

// ---------------- K4: combine partials + residual + ELU ---------------------
__global__ void k_out(float* __restrict__ out) {
    int g = blockIdx.x * blockDim.x + threadIdx.x;
    float v = g_h[g];
#pragma unroll
    for (int s = 0; s < SPLIT; ++s) v += g_part[s][g];
    out[g] = (v > 0.f) ? v : expm1f(v);
}

// ---------------- launch ----------------------------------------------------
extern "C" void kernel_launch(void* const* d_in, const int* in_sizes, int n_in,
                              void* d_out, int out_size) {
    (void)in_sizes; (void)n_in; (void)out_size;
    const float* x   = (const float*)d_in[0];
    const float* W   = (const float*)d_in[1];
    const float* a   = (const float*)d_in[2];
    const int*   adj = (const int*)d_in[3];
    float*       out = (float*)d_out;

    k_h    <<<N, 128>>>(x, W, a);
    k_stats<<<N / SROWS, 256>>>(adj);
    k_agg  <<<dim3(N / BM, SPLIT), 256>>>();
    k_out  <<<(N * D) / 256, 256>>>(out);
}

// round 5
// speedup vs baseline: 2.4989x; 1.4024x over previous
#include <cuda_runtime.h>
#include <cuda_bf16.h>
#include <math_constants.h>
#include <cstdint>

#define N      8192
#define D      128
#define THR    1e-4f
#define SPLIT  2
#define BK     32
#define NT     ((N / SPLIT) / BK)   // 128 K-iterations per CTA
#define SROWS  8

// ---------------- scratch (static device globals; no allocation) ------------
__device__ float    g_h[N * D];                    // 4 MB fp32 h (residual)
__device__ float    g_src[N], g_dst[N], g_Bz[N], g_Cz[N];
__device__ float4   g_rowc[N];                     // {fa, fb, Ta, Tb}
__device__ unsigned g_mask[(size_t)N * N / 32];    // 8 MB adjacency bits
__device__ __align__(16) __nv_bfloat16 g_hh[N * D];  // 2 MB h hi (row-major)
__device__ __align__(16) __nv_bfloat16 g_hl[N * D];  // 2 MB h lo (row-major)
__device__ float    g_part[SPLIT][N * D];          // 8 MB split-K partials

// smem tile geometry (bf16 element pitches; odd 16B-granule counts -> no LDSM conflicts)
#define APITCH 40     // 128 x 32 A tile rows padded 32->40 (80 B = 5 granules)
#define BPITCH 136    // 32 x 128 B tile rows padded 128->136 (272 B = 17 granules)
#define A_BYTES (128 * APITCH * 2)                 // 10240
#define B_BYTES (BK * BPITCH * 2)                  // 8704
#define BUF_BYTES (2 * A_BYTES + 2 * B_BYTES)      // 37888
#define SMEM_DYN  (2 * BUF_BYTES)                  // 75776 (double buffered)

// ---------------- PTX helpers -----------------------------------------------
__device__ __forceinline__ uint32_t smem_u32(const void* p) {
    uint32_t a;
    asm("{ .reg .u64 t; cvta.to.shared.u64 t, %1; cvt.u32.u64 %0, t; }"
        : "=r"(a) : "l"(p));
    return a;
}
__device__ __forceinline__ void ldsm4(uint32_t* r, uint32_t addr) {
    asm volatile("ldmatrix.sync.aligned.m8n8.x4.shared.b16 {%0,%1,%2,%3}, [%4];"
                 : "=r"(r[0]), "=r"(r[1]), "=r"(r[2]), "=r"(r[3]) : "r"(addr));
}
__device__ __forceinline__ void ldsm4t(uint32_t* r, uint32_t addr) {
    asm volatile("ldmatrix.sync.aligned.m8n8.x4.trans.shared.b16 {%0,%1,%2,%3}, [%4];"
                 : "=r"(r[0]), "=r"(r[1]), "=r"(r[2]), "=r"(r[3]) : "r"(addr));
}
__device__ __forceinline__ void mma16816(float* c, const uint32_t* a,
                                         const uint32_t* b) {
    asm volatile("mma.sync.aligned.m16n8k16.row.col.f32.bf16.bf16.f32 "
                 "{%0,%1,%2,%3}, {%4,%5,%6,%7}, {%8,%9}, {%0,%1,%2,%3};"
                 : "+f"(c[0]), "+f"(c[1]), "+f"(c[2]), "+f"(c[3])
                 : "r"(a[0]), "r"(a[1]), "r"(a[2]), "r"(a[3]),
                   "r"(b[0]), "r"(b[1]));
}

// ---------------- K1: h = X @ W + per-node scalars + bf16 hi/lo -------------
__global__ void k_h(const float* __restrict__ x,
                    const float* __restrict__ W,
                    const float* __restrict__ a) {
    int i = blockIdx.x;
    int k = threadIdx.x;

    __shared__ float xs[D];
    __shared__ float red[D];
    __shared__ float res[3];

    xs[k] = x[i * D + k];
    __syncthreads();

    float acc = 0.f;
#pragma unroll 16
    for (int c = 0; c < D; ++c)
        acc = fmaf(xs[c], W[c * D + k], acc);

    g_h[i * D + k] = acc;
    __nv_bfloat16 hi = __float2bfloat16(acc);
    g_hh[i * D + k] = hi;
    g_hl[i * D + k] = __float2bfloat16(acc - __bfloat162float(hi));

    float vals[3] = {acc, acc * a[k], acc * a[D + k]};
#pragma unroll
    for (int v = 0; v < 3; ++v) {
        red[k] = vals[v];
        __syncthreads();
        for (int st = 64; st > 0; st >>= 1) {
            if (k < st) red[k] += red[k + st];
            __syncthreads();
        }
        if (k == 0) res[v] = red[0];
        __syncthreads();
    }
    if (k == 0) {
        float rs = res[0], s = res[1], d = res[2];
        bool  nz = (rs != 0.0f);
        g_src[i] = s;
        g_dst[i] = d;
        g_Bz[i]  = nz ? __expf(d)        : 0.f;
        g_Cz[i]  = nz ? __expf(0.2f * d) : 0.f;
    }
}

// ---------------- K2: single-pass softmax stats + bitmask -------------------
__global__ void k_stats(const int* __restrict__ adj) {
    int row  = blockIdx.x * SROWS + (threadIdx.x >> 5);
    int lane = threadIdx.x & 31;

    __shared__ float sd[512], sb[512], sc[512];

    float src = g_src[row];
    float ea  = __expf(src);
    float eb  = __expf(0.2f * src);

    float s = 0.f, vm = 0.f;
    int   cnt = 0;
    const int* arow = adj + (size_t)row * N;

    for (int ch = 0; ch < N / 512; ++ch) {
        int jb = ch * 512;
        __syncthreads();
        for (int q = threadIdx.x; q < 512; q += 256) {
            sd[q] = g_dst[jb + q];
            sb[q] = g_Bz[jb + q];
            sc[q] = g_Cz[jb + q];
        }
        __syncthreads();
#pragma unroll 4
        for (int st = 0; st < 16; ++st) {
            int j = jb + st * 32 + lane;
            int a = arow[j];
            bool bit = (a > 0);
            unsigned bal = __ballot_sync(0xffffffffu, bit);
            if (lane == 0)
                g_mask[(size_t)row * (N / 32) + (j >> 5)] = bal;

            int   q   = st * 32 + lane;
            float dv  = sd[q];
            bool  pos = (src + dv) > 0.f;
            float b   = pos ? sb[q] : sc[q];
            float f   = pos ? ea    : eb;
            float v   = bit ? b * f : 0.f;
            s  += v;
            vm  = fmaxf(vm, v);
            cnt += (bit && b > 0.f) ? 1 : 0;
        }
    }
#pragma unroll
    for (int o = 16; o > 0; o >>= 1) {
        s   += __shfl_xor_sync(0xffffffffu, s, o);
        vm   = fmaxf(vm, __shfl_xor_sync(0xffffffffu, vm, o));
        cnt += __shfl_xor_sync(0xffffffffu, cnt, o);
    }
    if (lane == 0) {
        bool active = (vm > THR * s);
        float fa = 0.f, fb = 0.f, Ta = CUDART_INF_F, Tb = CUDART_INF_F;
        if (active) {
            float inv = 1.0f / s;
            float L   = (float)cnt;
            fa = ea * inv * L;
            fb = eb * inv * L;
            Ta = THR * s / ea;
            Tb = THR * s / eb;
        }
        g_rowc[row] = make_float4(fa, fb, Ta, Tb);
    }
}

// ---------------- K3: attention @ h via mma.sync bf16 hi/lo (3-pass) --------
__global__ void __launch_bounds__(256, 1) k_agg() {
    extern __shared__ __align__(16) char sm[];
    uint32_t smb = smem_u32(sm);

    int tid  = threadIdx.x;
    int lane = tid & 31;
    int wid  = tid >> 5;
    int ib     = blockIdx.x * 128;
    int split  = blockIdx.y;
    int jstart = split * (N / SPLIT);

    // weight-gen assignment: row gi, 16 consecutive j's
    int gi  = tid >> 1;
    int j16 = (tid & 1) << 4;
    float  src = g_src[ib + gi];
    float4 rc  = g_rowc[ib + gi];
    const unsigned* mrow = g_mask + (size_t)(ib + gi) * (N / 32);

    // warp tile: 4 x 2 grid of 32(m) x 64(n)
    int wm = (wid & 3) * 32;
    int wn = (wid >> 2) * 64;

    float acc[2][8][4];
#pragma unroll
    for (int mf = 0; mf < 2; ++mf)
#pragma unroll
        for (int nf = 0; nf < 8; ++nf)
#pragma unroll
            for (int q = 0; q < 4; ++q) acc[mf][nf][q] = 0.f;

    auto gen = [&](int t) {
        int b  = t & 1;
        int jb = jstart + t * BK;
        char* Ah = sm + b * BUF_BYTES;
        char* Al = Ah + A_BYTES;
        char* Bh = Ah + 2 * A_BYTES;
        char* Bl = Bh + B_BYTES;

        unsigned mw = mrow[jb >> 5] >> j16;
        const float2* pd = (const float2*)(g_dst + jb + j16);
        const float2* pb = (const float2*)(g_Bz  + jb + j16);
        const float2* pc = (const float2*)(g_Cz  + jb + j16);
        uint32_t* ah32 = (uint32_t*)Ah + gi * (APITCH / 2) + (j16 >> 1);
        uint32_t* al32 = (uint32_t*)Al + gi * (APITCH / 2) + (j16 >> 1);
#pragma unroll
        for (int u = 0; u < 8; ++u) {
            float2 dv = __ldg(&pd[u]);
            float2 bz = __ldg(&pb[u]);
            float2 cz = __ldg(&pc[u]);
            bool p0 = (src + dv.x) > 0.f;
            bool p1 = (src + dv.y) > 0.f;
            float b0 = p0 ? bz.x : cz.x,  b1 = p1 ? bz.y : cz.y;
            float T0 = p0 ? rc.z : rc.w,  T1 = p1 ? rc.z : rc.w;
            float f0 = p0 ? rc.x : rc.y,  f1 = p1 ? rc.x : rc.y;
            bool ok0 = (b0 >= T0) && ((mw >> (2 * u)) & 1u);
            bool ok1 = (b1 >= T1) && ((mw >> (2 * u + 1)) & 1u);
            float w0 = ok0 ? b0 * f0 : 0.f;
            float w1 = ok1 ? b1 * f1 : 0.f;
            uint32_t hp;
            asm("cvt.rn.bf16x2.f32 %0, %1, %2;" : "=r"(hp) : "f"(w1), "f"(w0));
            float h0 = __uint_as_float(hp << 16);
            float h1 = __uint_as_float(hp & 0xffff0000u);
            uint32_t lp;
            asm("cvt.rn.bf16x2.f32 %0, %1, %2;" : "=r"(lp) : "f"(w1 - h1), "f"(w0 - h0));
            ah32[u] = hp;
            al32[u] = lp;
        }
        // stage h tile [BK][128] hi/lo
#pragma unroll
        for (int q = 0; q < 2; ++q) {
            int idx = tid + q * 256;
            int r = idx >> 4, g = idx & 15;
            const uint4* s1 = (const uint4*)(g_hh + (size_t)(jb + r) * D + g * 8);
            const uint4* s2 = (const uint4*)(g_hl + (size_t)(jb + r) * D + g * 8);
            *(uint4*)(Bh + ((size_t)r * BPITCH + g * 8) * 2) = __ldg(s1);
            *(uint4*)(Bl + ((size_t)r * BPITCH + g * 8) * 2) = __ldg(s2);
        }
    };

    auto domma = [&](int t) {
        int b = t & 1;
        uint32_t Ah = smb + b * BUF_BYTES;
        uint32_t Al = Ah + A_BYTES;
        uint32_t Bh = Ah + 2 * A_BYTES;
        uint32_t Bl = Bh + B_BYTES;
#pragma unroll
        for (int ks = 0; ks < 2; ++ks) {
            int k0 = ks * 16;
            uint32_t ahf[2][4], alf[2][4];
#pragma unroll
            for (int mf = 0; mf < 2; ++mf) {
                uint32_t row = wm + mf * 16 + (lane & 15);
                uint32_t off = row * (APITCH * 2) + (k0 + ((lane >> 4) << 3)) * 2;
                ldsm4(ahf[mf], Ah + off);
                ldsm4(alf[mf], Al + off);
            }
#pragma unroll
            for (int nf2 = 0; nf2 < 4; ++nf2) {
                int n0 = wn + nf2 * 16;
                uint32_t r = k0 + (lane & 7) + ((lane >> 3) & 1) * 8;
                uint32_t c = n0 + ((lane >> 4) << 3);
                uint32_t off = r * (BPITCH * 2) + c * 2;
                uint32_t bh[4], bl[4];
                ldsm4t(bh, Bh + off);
                ldsm4t(bl, Bl + off);
#pragma unroll
                for (int mf = 0; mf < 2; ++mf) {
                    mma16816(acc[mf][nf2 * 2],     ahf[mf], bh);
                    mma16816(acc[mf][nf2 * 2],     ahf[mf], bl);
                    mma16816(acc[mf][nf2 * 2],     alf[mf], bh);
                    mma16816(acc[mf][nf2 * 2 + 1], ahf[mf], bh + 2);
                    mma16816(acc[mf][nf2 * 2 + 1], ahf[mf], bl + 2);
                    mma16816(acc[mf][nf2 * 2 + 1], alf[mf], bh + 2);
                }
            }
        }
    };

    gen(0);
    __syncthreads();
    for (int t = 0; t < NT; ++t) {
        if (t + 1 < NT) gen(t + 1);
        domma(t);
        __syncthreads();
    }

    // epilogue: write split partial
    int r0    = ib + wm + (lane >> 2);
    int cbase = wn + (lane & 3) * 2;
#pragma unroll
    for (int mf = 0; mf < 2; ++mf)
#pragma unroll
        for (int nf = 0; nf < 8; ++nf) {
            int row = r0 + mf * 16;
            int col = cbase + nf * 8;
            float* p = &g_part[split][(size_t)row * D + col];
            *(float2*)p             = make_float2(acc[mf][nf][0], acc[mf][nf][1]);
            *(float2*)(p + 8 * D)   = make_float2(acc[mf][nf][2], acc[mf][nf][3]);
        }
}

// ---------------- K4: combine partials + residual + ELU ---------------------
__global__ void k_out(float* __restrict__ out) {
    int g = blockIdx.x * blockDim.x + threadIdx.x;
    float v = g_h[g];
#pragma unroll
    for (int s = 0; s < SPLIT; ++s) v += g_part[s][g];
    out[g] = (v > 0.f) ? v : expm1f(v);
}

// ---------------- launch ----------------------------------------------------
extern "C" void kernel_launch(void* const* d_in, const int* in_sizes, int n_in,
                              void* d_out, int out_size) {
    (void)in_sizes; (void)n_in; (void)out_size;
    const float* x   = (const float*)d_in[0];
    const float* W   = (const float*)d_in[1];
    const float* a   = (const float*)d_in[2];
    const int*   adj = (const int*)d_in[3];
    float*       out = (float*)d_out;

    cudaFuncSetAttribute(k_agg, cudaFuncAttributeMaxDynamicSharedMemorySize, SMEM_DYN);

    k_h    <<<N, 128>>>(x, W, a);
    k_stats<<<N / SROWS, 256>>>(adj);
    k_agg  <<<dim3(N / 128, SPLIT), 256, SMEM_DYN>>>();
    k_out  <<<(N * D) / 256, 256>>>(out);
}

// round 6
// speedup vs baseline: 3.1167x; 1.2472x over previous
#include <cuda_runtime.h>
#include <cuda_bf16.h>
#include <math_constants.h>
#include <cstdint>

#define N      8192
#define D      128
#define THR    1e-4f
#define SPLIT  4
#define BK     32
#define NT     ((N / SPLIT) / BK)   // 64 K-iterations per CTA
#define SROWS  8

// ---------------- scratch (static device globals; no allocation) ------------
__device__ float    g_h[N * D];                    // 4 MB fp32 h (residual)
__device__ float    g_src[N], g_dst[N], g_Bz[N], g_Cz[N];
__device__ float4   g_rowc[N];                     // {fa, fb, Ta, Tb}
__device__ unsigned g_mask[(size_t)N * N / 32];    // 8 MB adjacency bits
__device__ __align__(16) __nv_bfloat16 g_hh[N * D];  // 2 MB h hi (row-major)
__device__ __align__(16) __nv_bfloat16 g_hl[N * D];  // 2 MB h lo (row-major)
__device__ float    g_part[SPLIT][N * D];          // 16 MB split-K partials

// smem tile geometry (bf16 pitches; odd 16B-granule counts -> LDSM conflict-free)
#define APITCH 40     // 128 x 32 A rows padded 32->40
#define BPITCH 136    // 32 x 128 B rows padded 128->136
#define A_BYTES (128 * APITCH * 2)                 // 10240
#define B_BYTES (BK * BPITCH * 2)                  // 8704
#define BUF_BYTES (2 * A_BYTES + 2 * B_BYTES)      // 37888
#define SMEM_DYN  (2 * BUF_BYTES)                  // 75776 (double buffered)

// ---------------- PTX helpers -----------------------------------------------
__device__ __forceinline__ uint32_t smem_u32(const void* p) {
    uint32_t a;
    asm("{ .reg .u64 t; cvta.to.shared.u64 t, %1; cvt.u32.u64 %0, t; }"
        : "=r"(a) : "l"(p));
    return a;
}
__device__ __forceinline__ void ldsm4(uint32_t* r, uint32_t addr) {
    asm volatile("ldmatrix.sync.aligned.m8n8.x4.shared.b16 {%0,%1,%2,%3}, [%4];"
                 : "=r"(r[0]), "=r"(r[1]), "=r"(r[2]), "=r"(r[3]) : "r"(addr));
}
__device__ __forceinline__ void ldsm4t(uint32_t* r, uint32_t addr) {
    asm volatile("ldmatrix.sync.aligned.m8n8.x4.trans.shared.b16 {%0,%1,%2,%3}, [%4];"
                 : "=r"(r[0]), "=r"(r[1]), "=r"(r[2]), "=r"(r[3]) : "r"(addr));
}
__device__ __forceinline__ void mma16816(float* c, const uint32_t* a,
                                         const uint32_t* b) {
    asm volatile("mma.sync.aligned.m16n8k16.row.col.f32.bf16.bf16.f32 "
                 "{%0,%1,%2,%3}, {%4,%5,%6,%7}, {%8,%9}, {%0,%1,%2,%3};"
                 : "+f"(c[0]), "+f"(c[1]), "+f"(c[2]), "+f"(c[3])
                 : "r"(a[0]), "r"(a[1]), "r"(a[2]), "r"(a[3]),
                   "r"(b[0]), "r"(b[1]));
}

// ---------------- K1: h = X @ W + per-node scalars + bf16 hi/lo -------------
__global__ void k_h(const float* __restrict__ x,
                    const float* __restrict__ W,
                    const float* __restrict__ a) {
    int i = blockIdx.x;
    int k = threadIdx.x;

    __shared__ float xs[D];
    __shared__ float red[D];
    __shared__ float res[3];

    xs[k] = x[i * D + k];
    __syncthreads();

    float acc = 0.f;
#pragma unroll 16
    for (int c = 0; c < D; ++c)
        acc = fmaf(xs[c], W[c * D + k], acc);

    g_h[i * D + k] = acc;
    __nv_bfloat16 hi = __float2bfloat16(acc);
    g_hh[i * D + k] = hi;
    g_hl[i * D + k] = __float2bfloat16(acc - __bfloat162float(hi));

    float vals[3] = {acc, acc * a[k], acc * a[D + k]};
#pragma unroll
    for (int v = 0; v < 3; ++v) {
        red[k] = vals[v];
        __syncthreads();
        for (int st = 64; st > 0; st >>= 1) {
            if (k < st) red[k] += red[k + st];
            __syncthreads();
        }
        if (k == 0) res[v] = red[0];
        __syncthreads();
    }
    if (k == 0) {
        float rs = res[0], s = res[1], d = res[2];
        bool  nz = (rs != 0.0f);
        g_src[i] = s;
        g_dst[i] = d;
        g_Bz[i]  = nz ? __expf(d)        : 0.f;
        g_Cz[i]  = nz ? __expf(0.2f * d) : 0.f;
    }
}

// ---------------- K2: single-pass softmax stats + bitmask (int4 + shfl-pack)
__global__ void k_stats(const int* __restrict__ adj) {
    int row  = blockIdx.x * SROWS + (threadIdx.x >> 5);
    int lane = threadIdx.x & 31;

    float src = g_src[row];
    float ea  = __expf(src);
    float eb  = __expf(0.2f * src);

    float s = 0.f, vm = 0.f;
    int   cnt = 0;
    const int4* arow = (const int4*)(adj + (size_t)row * N);
    unsigned* mrow = g_mask + (size_t)row * (N / 32);

    for (int blk = 0; blk < N / 128; ++blk) {
        int j0 = blk * 128 + lane * 4;
        int4 av = arow[blk * 32 + lane];
        float4 dv = __ldg((const float4*)(g_dst + j0));
        float4 bz = __ldg((const float4*)(g_Bz  + j0));
        float4 cz = __ldg((const float4*)(g_Cz  + j0));

        unsigned nib = (av.x > 0) | ((av.y > 0) << 1) |
                       ((av.z > 0) << 2) | ((av.w > 0) << 3);
        unsigned v = nib;
        v |= __shfl_down_sync(0xffffffffu, v, 1) << 4;
        v |= __shfl_down_sync(0xffffffffu, v, 2) << 8;
        v |= __shfl_down_sync(0xffffffffu, v, 4) << 16;
        if ((lane & 7) == 0)
            mrow[blk * 4 + (lane >> 3)] = v;

        float da[4] = {dv.x, dv.y, dv.z, dv.w};
        float ba[4] = {bz.x, bz.y, bz.z, bz.w};
        float ca[4] = {cz.x, cz.y, cz.z, cz.w};
#pragma unroll
        for (int u = 0; u < 4; ++u) {
            bool  bit = (nib >> u) & 1u;
            bool  pos = (src + da[u]) > 0.f;
            float b   = pos ? ba[u] : ca[u];
            float f   = pos ? ea    : eb;
            float val = bit ? b * f : 0.f;
            s  += val;
            vm  = fmaxf(vm, val);
            cnt += (bit && b > 0.f) ? 1 : 0;
        }
    }
#pragma unroll
    for (int o = 16; o > 0; o >>= 1) {
        s   += __shfl_xor_sync(0xffffffffu, s, o);
        vm   = fmaxf(vm, __shfl_xor_sync(0xffffffffu, vm, o));
        cnt += __shfl_xor_sync(0xffffffffu, cnt, o);
    }
    if (lane == 0) {
        bool active = (vm > THR * s);
        float fa = 0.f, fb = 0.f, Ta = CUDART_INF_F, Tb = CUDART_INF_F;
        if (active) {
            float inv = 1.0f / s;
            float L   = (float)cnt;
            fa = ea * inv * L;
            fb = eb * inv * L;
            Ta = THR * s / ea;
            Tb = THR * s / eb;
        }
        g_rowc[row] = make_float4(fa, fb, Ta, Tb);
    }
}

// ---------------- K3: attention @ h via mma.sync bf16 hi/lo (3-pass) --------
__global__ void __launch_bounds__(256, 2) k_agg() {
    extern __shared__ __align__(16) char sm[];
    uint32_t smb = smem_u32(sm);

    int tid  = threadIdx.x;
    int lane = tid & 31;
    int wid  = tid >> 5;
    int ib     = blockIdx.x * 128;
    int split  = blockIdx.y;
    int jstart = split * (N / SPLIT);

    // weight-gen assignment: row gi, 16 consecutive j's
    int gi  = tid >> 1;
    int j16 = (tid & 1) << 4;
    float  src = g_src[ib + gi];
    float4 rc  = g_rowc[ib + gi];
    const unsigned* mrow = g_mask + (size_t)(ib + gi) * (N / 32);

    // warp tile: 4 x 2 grid of 32(m) x 64(n)
    int wm = (wid & 3) * 32;
    int wn = (wid >> 2) * 64;

    float acc[2][8][4];
#pragma unroll
    for (int mf = 0; mf < 2; ++mf)
#pragma unroll
        for (int nf = 0; nf < 8; ++nf)
#pragma unroll
            for (int q = 0; q < 4; ++q) acc[mf][nf][q] = 0.f;

    auto gen = [&](int t) {
        int b  = t & 1;
        int jb = jstart + t * BK;
        char* Ah = sm + b * BUF_BYTES;
        char* Al = Ah + A_BYTES;
        char* Bh = Ah + 2 * A_BYTES;
        char* Bl = Bh + B_BYTES;

        unsigned mw = mrow[jb >> 5] >> j16;
        const float2* pd = (const float2*)(g_dst + jb + j16);
        const float2* pb = (const float2*)(g_Bz  + jb + j16);
        const float2* pc = (const float2*)(g_Cz  + jb + j16);
        uint32_t* ah32 = (uint32_t*)Ah + gi * (APITCH / 2) + (j16 >> 1);
        uint32_t* al32 = (uint32_t*)Al + gi * (APITCH / 2) + (j16 >> 1);
#pragma unroll
        for (int u = 0; u < 8; ++u) {
            float2 dv = __ldg(&pd[u]);
            float2 bz = __ldg(&pb[u]);
            float2 cz = __ldg(&pc[u]);
            bool p0 = (src + dv.x) > 0.f;
            bool p1 = (src + dv.y) > 0.f;
            float b0 = p0 ? bz.x : cz.x,  b1 = p1 ? bz.y : cz.y;
            float T0 = p0 ? rc.z : rc.w,  T1 = p1 ? rc.z : rc.w;
            float f0 = p0 ? rc.x : rc.y,  f1 = p1 ? rc.x : rc.y;
            bool ok0 = (b0 >= T0) && ((mw >> (2 * u)) & 1u);
            bool ok1 = (b1 >= T1) && ((mw >> (2 * u + 1)) & 1u);
            float w0 = ok0 ? b0 * f0 : 0.f;
            float w1 = ok1 ? b1 * f1 : 0.f;
            uint32_t hp;
            asm("cvt.rn.bf16x2.f32 %0, %1, %2;" : "=r"(hp) : "f"(w1), "f"(w0));
            float h0 = __uint_as_float(hp << 16);
            float h1 = __uint_as_float(hp & 0xffff0000u);
            uint32_t lp;
            asm("cvt.rn.bf16x2.f32 %0, %1, %2;" : "=r"(lp) : "f"(w1 - h1), "f"(w0 - h0));
            ah32[u] = hp;
            al32[u] = lp;
        }
        // stage h tile [BK][128] hi/lo
#pragma unroll
        for (int q = 0; q < 2; ++q) {
            int idx = tid + q * 256;
            int r = idx >> 4, g = idx & 15;
            const uint4* s1 = (const uint4*)(g_hh + (size_t)(jb + r) * D + g * 8);
            const uint4* s2 = (const uint4*)(g_hl + (size_t)(jb + r) * D + g * 8);
            *(uint4*)(Bh + ((size_t)r * BPITCH + g * 8) * 2) = __ldg(s1);
            *(uint4*)(Bl + ((size_t)r * BPITCH + g * 8) * 2) = __ldg(s2);
        }
    };

    auto domma = [&](int t) {
        int b = t & 1;
        uint32_t Ah = smb + b * BUF_BYTES;
        uint32_t Al = Ah + A_BYTES;
        uint32_t Bh = Ah + 2 * A_BYTES;
        uint32_t Bl = Bh + B_BYTES;
#pragma unroll
        for (int ks = 0; ks < 2; ++ks) {
            int k0 = ks * 16;
            uint32_t ahf[2][4], alf[2][4];
#pragma unroll
            for (int mf = 0; mf < 2; ++mf) {
                uint32_t row = wm + mf * 16 + (lane & 15);
                uint32_t off = row * (APITCH * 2) + (k0 + ((lane >> 4) << 3)) * 2;
                ldsm4(ahf[mf], Ah + off);
                ldsm4(alf[mf], Al + off);
            }
#pragma unroll
            for (int nf2 = 0; nf2 < 4; ++nf2) {
                int n0 = wn + nf2 * 16;
                uint32_t r = k0 + (lane & 7) + ((lane >> 3) & 1) * 8;
                uint32_t c = n0 + ((lane >> 4) << 3);
                uint32_t off = r * (BPITCH * 2) + c * 2;
                uint32_t bh[4], bl[4];
                ldsm4t(bh, Bh + off);
                ldsm4t(bl, Bl + off);
#pragma unroll
                for (int mf = 0; mf < 2; ++mf) {
                    mma16816(acc[mf][nf2 * 2],     ahf[mf], bh);
                    mma16816(acc[mf][nf2 * 2],     ahf[mf], bl);
                    mma16816(acc[mf][nf2 * 2],     alf[mf], bh);
                    mma16816(acc[mf][nf2 * 2 + 1], ahf[mf], bh + 2);
                    mma16816(acc[mf][nf2 * 2 + 1], ahf[mf], bl + 2);
                    mma16816(acc[mf][nf2 * 2 + 1], alf[mf], bh + 2);
                }
            }
        }
    };

    gen(0);
    __syncthreads();
    for (int t = 0; t < NT; ++t) {
        if (t + 1 < NT) gen(t + 1);
        domma(t);
        __syncthreads();
    }

    // epilogue: write split partial
    int r0    = ib + wm + (lane >> 2);
    int cbase = wn + (lane & 3) * 2;
#pragma unroll
    for (int mf = 0; mf < 2; ++mf)
#pragma unroll
        for (int nf = 0; nf < 8; ++nf) {
            int row = r0 + mf * 16;
            int col = cbase + nf * 8;
            float* p = &g_part[split][(size_t)row * D + col];
            *(float2*)p             = make_float2(acc[mf][nf][0], acc[mf][nf][1]);
            *(float2*)(p + 8 * D)   = make_float2(acc[mf][nf][2], acc[mf][nf][3]);
        }
}

// ---------------- K4: combine partials + residual + ELU ---------------------
__global__ void k_out(float* __restrict__ out) {
    int g = blockIdx.x * blockDim.x + threadIdx.x;
    float v = g_h[g];
#pragma unroll
    for (int s = 0; s < SPLIT; ++s) v += g_part[s][g];
    out[g] = (v > 0.f) ? v : expm1f(v);
}

// ---------------- launch ----------------------------------------------------
extern "C" void kernel_launch(void* const* d_in, const int* in_sizes, int n_in,
                              void* d_out, int out_size) {
    (void)in_sizes; (void)n_in; (void)out_size;
    const float* x   = (const float*)d_in[0];
    const float* W   = (const float*)d_in[1];
    const float* a   = (const float*)d_in[2];
    const int*   adj = (const int*)d_in[3];
    float*       out = (float*)d_out;

    cudaFuncSetAttribute(k_agg, cudaFuncAttributeMaxDynamicSharedMemorySize, SMEM_DYN);

    k_h    <<<N, 128>>>(x, W, a);
    k_stats<<<N / SROWS, 256>>>(adj);
    k_agg  <<<dim3(N / 128, SPLIT), 256, SMEM_DYN>>>();
    k_out  <<<(N * D) / 256, 256>>>(out);
}

// round 7
// speedup vs baseline: 3.2726x; 1.0500x over previous
#include <cuda_runtime.h>
#include <cuda_bf16.h>
#include <math_constants.h>
#include <cstdint>

#define N      8192
#define D      128
#define THR    1e-4f
#define SPLIT  4
#define BK     32
#define JR     (N / SPLIT)          // 2048 j per CTA
#define NT     (JR / BK)            // 64 K-iterations per CTA
#define SROWS  8

// ---------------- scratch (static device globals; no allocation) ------------
__device__ float    g_h[N * D];                    // 4 MB fp32 h (residual)
__device__ float    g_src[N], g_dst[N], g_Bz[N], g_Cz[N];
__device__ float4   g_rowc[N];                     // {fa, fb, Ta, Tb}
__device__ unsigned g_mask[(size_t)N * N / 32];    // 8 MB adjacency bits
__device__ __align__(16) __nv_bfloat16 g_hh[N * D];  // 2 MB h hi (row-major)
__device__ __align__(16) __nv_bfloat16 g_hl[N * D];  // 2 MB h lo (row-major)
__device__ float    g_part[SPLIT][N * D];          // 16 MB split-K partials

// smem tile geometry (bf16 pitches; odd 16B-granule counts -> LDSM conflict-free)
#define APITCH 40
#define BPITCH 136
#define A_BYTES (128 * APITCH * 2)                 // 10240
#define B_BYTES (BK * BPITCH * 2)                  // 8704
#define BUF_BYTES (2 * A_BYTES + 2 * B_BYTES)      // 37888
#define SM_TAB    (2 * BUF_BYTES)                  // 75776 (float tables)
#define SMEM_DYN  (SM_TAB + 3 * JR * 4)            // 100352

// ---------------- PTX helpers -----------------------------------------------
__device__ __forceinline__ uint32_t smem_u32(const void* p) {
    uint32_t a;
    asm("{ .reg .u64 t; cvta.to.shared.u64 t, %1; cvt.u32.u64 %0, t; }"
        : "=r"(a) : "l"(p));
    return a;
}
__device__ __forceinline__ void cpa16(uint32_t dst, const void* src) {
    asm volatile("cp.async.cg.shared.global [%0], [%1], 16;"
                 :: "r"(dst), "l"(src) : "memory");
}
#define CPA_COMMIT() asm volatile("cp.async.commit_group;" ::: "memory")
#define CPA_WAIT0()  asm volatile("cp.async.wait_group 0;" ::: "memory")

__device__ __forceinline__ void ldsm4(uint32_t* r, uint32_t addr) {
    asm volatile("ldmatrix.sync.aligned.m8n8.x4.shared.b16 {%0,%1,%2,%3}, [%4];"
                 : "=r"(r[0]), "=r"(r[1]), "=r"(r[2]), "=r"(r[3]) : "r"(addr));
}
__device__ __forceinline__ void ldsm4t(uint32_t* r, uint32_t addr) {
    asm volatile("ldmatrix.sync.aligned.m8n8.x4.trans.shared.b16 {%0,%1,%2,%3}, [%4];"
                 : "=r"(r[0]), "=r"(r[1]), "=r"(r[2]), "=r"(r[3]) : "r"(addr));
}
__device__ __forceinline__ void mma16816(float* c, const uint32_t* a,
                                         const uint32_t* b) {
    asm volatile("mma.sync.aligned.m16n8k16.row.col.f32.bf16.bf16.f32 "
                 "{%0,%1,%2,%3}, {%4,%5,%6,%7}, {%8,%9}, {%0,%1,%2,%3};"
                 : "+f"(c[0]), "+f"(c[1]), "+f"(c[2]), "+f"(c[3])
                 : "r"(a[0]), "r"(a[1]), "r"(a[2]), "r"(a[3]),
                   "r"(b[0]), "r"(b[1]));
}

// ---------------- K1: h = X @ W + per-node scalars + bf16 hi/lo -------------
__global__ void k_h(const float* __restrict__ x,
                    const float* __restrict__ W,
                    const float* __restrict__ a) {
    int i = blockIdx.x;
    int k = threadIdx.x;

    __shared__ float xs[D];
    __shared__ float red[D];
    __shared__ float res[3];

    xs[k] = x[i * D + k];
    __syncthreads();

    float acc = 0.f;
#pragma unroll 16
    for (int c = 0; c < D; ++c)
        acc = fmaf(xs[c], W[c * D + k], acc);

    g_h[i * D + k] = acc;
    __nv_bfloat16 hi = __float2bfloat16(acc);
    g_hh[i * D + k] = hi;
    g_hl[i * D + k] = __float2bfloat16(acc - __bfloat162float(hi));

    float vals[3] = {acc, acc * a[k], acc * a[D + k]};
#pragma unroll
    for (int v = 0; v < 3; ++v) {
        red[k] = vals[v];
        __syncthreads();
        for (int st = 64; st > 0; st >>= 1) {
            if (k < st) red[k] += red[k + st];
            __syncthreads();
        }
        if (k == 0) res[v] = red[0];
        __syncthreads();
    }
    if (k == 0) {
        float rs = res[0], s = res[1], d = res[2];
        bool  nz = (rs != 0.0f);
        g_src[i] = s;
        g_dst[i] = d;
        g_Bz[i]  = nz ? __expf(d)        : 0.f;
        g_Cz[i]  = nz ? __expf(0.2f * d) : 0.f;
    }
}

// ---------------- K2: single-pass softmax stats + bitmask (2-way unroll) ----
__global__ void k_stats(const int* __restrict__ adj) {
    int row  = blockIdx.x * SROWS + (threadIdx.x >> 5);
    int lane = threadIdx.x & 31;

    float src = g_src[row];
    float ea  = __expf(src);
    float eb  = __expf(0.2f * src);

    float s = 0.f, vm = 0.f;
    int   cnt = 0;
    const int4* arow = (const int4*)(adj + (size_t)row * N);
    unsigned* mrow = g_mask + (size_t)row * (N / 32);

    for (int blk2 = 0; blk2 < N / 256; ++blk2) {
        int4 av0 = arow[blk2 * 64 + lane];
        int4 av1 = arow[blk2 * 64 + 32 + lane];
#pragma unroll
        for (int half = 0; half < 2; ++half) {
            int4 av = half ? av1 : av0;
            int blk = blk2 * 2 + half;
            int j0  = blk * 128 + lane * 4;
            float4 dv = __ldg((const float4*)(g_dst + j0));
            float4 bz = __ldg((const float4*)(g_Bz  + j0));
            float4 cz = __ldg((const float4*)(g_Cz  + j0));

            unsigned nib = (av.x > 0) | ((av.y > 0) << 1) |
                           ((av.z > 0) << 2) | ((av.w > 0) << 3);
            unsigned v = nib;
            v |= __shfl_down_sync(0xffffffffu, v, 1) << 4;
            v |= __shfl_down_sync(0xffffffffu, v, 2) << 8;
            v |= __shfl_down_sync(0xffffffffu, v, 4) << 16;
            if ((lane & 7) == 0)
                mrow[blk * 4 + (lane >> 3)] = v;

            float da[4] = {dv.x, dv.y, dv.z, dv.w};
            float ba[4] = {bz.x, bz.y, bz.z, bz.w};
            float ca[4] = {cz.x, cz.y, cz.z, cz.w};
#pragma unroll
            for (int u = 0; u < 4; ++u) {
                bool  bit = (nib >> u) & 1u;
                bool  pos = (src + da[u]) > 0.f;
                float b   = pos ? ba[u] : ca[u];
                float f   = pos ? ea    : eb;
                float val = bit ? b * f : 0.f;
                s  += val;
                vm  = fmaxf(vm, val);
                cnt += (bit && b > 0.f) ? 1 : 0;
            }
        }
    }
#pragma unroll
    for (int o = 16; o > 0; o >>= 1) {
        s   += __shfl_xor_sync(0xffffffffu, s, o);
        vm   = fmaxf(vm, __shfl_xor_sync(0xffffffffu, vm, o));
        cnt += __shfl_xor_sync(0xffffffffu, cnt, o);
    }
    if (lane == 0) {
        bool active = (vm > THR * s);
        float fa = 0.f, fb = 0.f, Ta = CUDART_INF_F, Tb = CUDART_INF_F;
        if (active) {
            float inv = 1.0f / s;
            float L   = (float)cnt;
            fa = ea * inv * L;
            fb = eb * inv * L;
            Ta = THR * s / ea;
            Tb = THR * s / eb;
        }
        g_rowc[row] = make_float4(fa, fb, Ta, Tb);
    }
}

// ---------------- K3: attention @ h via mma.sync bf16 hi/lo (3-pass) --------
__global__ void __launch_bounds__(256, 2) k_agg() {
    extern __shared__ __align__(16) char sm[];
    uint32_t smb = smem_u32(sm);

    int tid  = threadIdx.x;
    int lane = tid & 31;
    int wid  = tid >> 5;
    int ib     = blockIdx.x * 128;
    int split  = blockIdx.y;
    int jstart = split * JR;

    float* s_dst = (float*)(sm + SM_TAB);
    float* s_bz  = s_dst + JR;
    float* s_cz  = s_bz  + JR;

    // weight-gen assignment: row gi, 16 consecutive j's
    int gi  = tid >> 1;
    int j16 = (tid & 1) << 4;
    float  src = g_src[ib + gi];
    float4 rc  = g_rowc[ib + gi];
    const unsigned* mrow = g_mask + (size_t)(ib + gi) * (N / 32) + (jstart >> 5);

    // warp tile: 4 x 2 grid of 32(m) x 64(n)
    int wm = (wid & 3) * 32;
    int wn = (wid >> 2) * 64;

    float acc[2][8][4];
#pragma unroll
    for (int mf = 0; mf < 2; ++mf)
#pragma unroll
        for (int nf = 0; nf < 8; ++nf)
#pragma unroll
            for (int q = 0; q < 4; ++q) acc[mf][nf][q] = 0.f;

    auto loadB = [&](int t) {   // async global->shared, 1 group
        int b  = t & 1;
        int jb = jstart + t * BK;
        uint32_t Bh = smb + b * BUF_BYTES + 2 * A_BYTES;
        uint32_t Bl = Bh + B_BYTES;
#pragma unroll
        for (int q = 0; q < 2; ++q) {
            int idx = tid + q * 256;
            int r = idx >> 4, g = idx & 15;
            uint32_t doff = (uint32_t)(r * BPITCH + g * 8) * 2;
            cpa16(Bh + doff, g_hh + (size_t)(jb + r) * D + g * 8);
            cpa16(Bl + doff, g_hl + (size_t)(jb + r) * D + g * 8);
        }
        CPA_COMMIT();
    };

    auto gen_store = [&](int t, unsigned mw_full) {
        int b = t & 1;
        char* Ah = sm + b * BUF_BYTES;
        char* Al = Ah + A_BYTES;
        unsigned mw = mw_full >> j16;
        int lj = t * BK + j16;
        const float4* td = (const float4*)(s_dst + lj);
        const float4* tb = (const float4*)(s_bz  + lj);
        const float4* tc = (const float4*)(s_cz  + lj);
        uint32_t* ah32 = (uint32_t*)Ah + gi * (APITCH / 2) + (j16 >> 1);
        uint32_t* al32 = (uint32_t*)Al + gi * (APITCH / 2) + (j16 >> 1);
#pragma unroll
        for (int e = 0; e < 4; ++e) {
            float4 dv = td[e];
            float4 bz = tb[e];
            float4 cz = tc[e];
            float da[4] = {dv.x, dv.y, dv.z, dv.w};
            float ba[4] = {bz.x, bz.y, bz.z, bz.w};
            float ca[4] = {cz.x, cz.y, cz.z, cz.w};
            float w[4];
#pragma unroll
            for (int k = 0; k < 4; ++k) {
                bool  pos = (src + da[k]) > 0.f;
                float bb  = pos ? ba[k] : ca[k];
                float T   = pos ? rc.z  : rc.w;
                float f   = pos ? rc.x  : rc.y;
                bool  ok  = (bb >= T) && ((mw >> (e * 4 + k)) & 1u);
                w[k] = ok ? bb * f : 0.f;
            }
            uint32_t hp0, hp1, lp0, lp1;
            asm("cvt.rn.bf16x2.f32 %0, %1, %2;" : "=r"(hp0) : "f"(w[1]), "f"(w[0]));
            asm("cvt.rn.bf16x2.f32 %0, %1, %2;" : "=r"(hp1) : "f"(w[3]), "f"(w[2]));
            float r0 = __uint_as_float(hp0 << 16);
            float r1 = __uint_as_float(hp0 & 0xffff0000u);
            float r2 = __uint_as_float(hp1 << 16);
            float r3 = __uint_as_float(hp1 & 0xffff0000u);
            asm("cvt.rn.bf16x2.f32 %0, %1, %2;" : "=r"(lp0) : "f"(w[1] - r1), "f"(w[0] - r0));
            asm("cvt.rn.bf16x2.f32 %0, %1, %2;" : "=r"(lp1) : "f"(w[3] - r3), "f"(w[2] - r2));
            *(uint2*)&ah32[e * 2] = make_uint2(hp0, hp1);
            *(uint2*)&al32[e * 2] = make_uint2(lp0, lp1);
        }
    };

    auto domma = [&](int t) {
        int b = t & 1;
        uint32_t Ah = smb + b * BUF_BYTES;
        uint32_t Al = Ah + A_BYTES;
        uint32_t Bh = Ah + 2 * A_BYTES;
        uint32_t Bl = Bh + B_BYTES;
#pragma unroll
        for (int ks = 0; ks < 2; ++ks) {
            int k0 = ks * 16;
            uint32_t ahf[2][4], alf[2][4];
#pragma unroll
            for (int mf = 0; mf < 2; ++mf) {
                uint32_t row = wm + mf * 16 + (lane & 15);
                uint32_t off = row * (APITCH * 2) + (k0 + ((lane >> 4) << 3)) * 2;
                ldsm4(ahf[mf], Ah + off);
                ldsm4(alf[mf], Al + off);
            }
#pragma unroll
            for (int nf2 = 0; nf2 < 4; ++nf2) {
                int n0 = wn + nf2 * 16;
                uint32_t r = k0 + (lane & 7) + ((lane >> 3) & 1) * 8;
                uint32_t c = n0 + ((lane >> 4) << 3);
                uint32_t off = r * (BPITCH * 2) + c * 2;
                uint32_t bh[4], bl[4];
                ldsm4t(bh, Bh + off);
                ldsm4t(bl, Bl + off);
#pragma unroll
                for (int mf = 0; mf < 2; ++mf) {
                    mma16816(acc[mf][nf2 * 2],     ahf[mf], bh);
                    mma16816(acc[mf][nf2 * 2],     ahf[mf], bl);
                    mma16816(acc[mf][nf2 * 2],     alf[mf], bh);
                    mma16816(acc[mf][nf2 * 2 + 1], ahf[mf], bh + 2);
                    mma16816(acc[mf][nf2 * 2 + 1], ahf[mf], bl + 2);
                    mma16816(acc[mf][nf2 * 2 + 1], alf[mf], bh + 2);
                }
            }
        }
    };

    // ---- prologue: B(0) async, stage tables, A(0) -------------------------
    loadB(0);
    {
        const float4* gd = (const float4*)(g_dst + jstart);
        const float4* gb = (const float4*)(g_Bz  + jstart);
        const float4* gc = (const float4*)(g_Cz  + jstart);
#pragma unroll
        for (int q = 0; q < 2; ++q) {
            int idx = tid + q * 256;
            ((float4*)s_dst)[idx] = __ldg(&gd[idx]);
            ((float4*)s_bz)[idx]  = __ldg(&gb[idx]);
            ((float4*)s_cz)[idx]  = __ldg(&gc[idx]);
        }
    }
    __syncthreads();                 // tables ready
    gen_store(0, __ldg(&mrow[0]));

    // ---- main pipeline ------------------------------------------------------
    for (int t = 0; t < NT; ++t) {
        CPA_WAIT0();                 // B(t) copies (this thread) done
        __syncthreads();             // A(t)+B(t) visible; domma(t-1) fenced
        unsigned mwn = 0;
        if (t + 1 < NT) {
            mwn = __ldg(&mrow[t + 1]);
            loadB(t + 1);
        }
        domma(t);
        if (t + 1 < NT) gen_store(t + 1, mwn);
    }

    // epilogue: write split partial
    int r0    = ib + wm + (lane >> 2);
    int cbase = wn + (lane & 3) * 2;
#pragma unroll
    for (int mf = 0; mf < 2; ++mf)
#pragma unroll
        for (int nf = 0; nf < 8; ++nf) {
            int row = r0 + mf * 16;
            int col = cbase + nf * 8;
            float* p = &g_part[split][(size_t)row * D + col];
            *(float2*)p             = make_float2(acc[mf][nf][0], acc[mf][nf][1]);
            *(float2*)(p + 8 * D)   = make_float2(acc[mf][nf][2], acc[mf][nf][3]);
        }
}

// ---------------- K4: combine partials + residual + ELU ---------------------
__global__ void k_out(float* __restrict__ out) {
    int g = blockIdx.x * blockDim.x + threadIdx.x;
    float v = g_h[g];
#pragma unroll
    for (int s = 0; s < SPLIT; ++s) v += g_part[s][g];
    out[g] = (v > 0.f) ? v : expm1f(v);
}

// ---------------- launch ----------------------------------------------------
extern "C" void kernel_launch(void* const* d_in, const int* in_sizes, int n_in,
                              void* d_out, int out_size) {
    (void)in_sizes; (void)n_in; (void)out_size;
    const float* x   = (const float*)d_in[0];
    const float* W   = (const float*)d_in[1];
    const float* a   = (const float*)d_in[2];
    const int*   adj = (const int*)d_in[3];
    float*       out = (float*)d_out;

    cudaFuncSetAttribute(k_agg, cudaFuncAttributeMaxDynamicSharedMemorySize, SMEM_DYN);

    k_h    <<<N, 128>>>(x, W, a);
    k_stats<<<N / SROWS, 256>>>(adj);
    k_agg  <<<dim3(N / 128, SPLIT), 256, SMEM_DYN>>>();
    k_out  <<<(N * D) / 256, 256>>>(out);
}

// round 8
// speedup vs baseline: 3.5954x; 1.0986x over previous
#include <cuda_runtime.h>
#include <cuda_bf16.h>
#include <math_constants.h>
#include <cstdint>

#define N      8192
#define D      128
#define THR    1e-4f
#define SPLIT  16
#define BK     32
#define JR     (N / SPLIT)          // 512 j per unit
#define NT     (JR / BK)            // 16 K-iterations per unit
#define NUNITS (64 * SPLIT)         // 1024 work units
#define NCTA   296
#define SROWS  8

// ---------------- scratch (static device globals; no allocation) ------------
__device__ float    g_h[N * D];                    // 4 MB fp32 h (residual)
__device__ float    g_src[N], g_Bz[N], g_Cz[N];
__device__ float4   g_rowc[N];                     // {eaF, ebF, T3, -}
__device__ unsigned g_mask[(size_t)N * N / 32];    // 8 MB adjacency bits
__device__ __align__(16) __nv_bfloat16 g_hh[N * D];  // 2 MB h hi
__device__ __align__(16) __nv_bfloat16 g_hl[N * D];  // 2 MB h lo
__device__ float    g_part[SPLIT][N * D];          // 64 MB split-K partials
__device__ unsigned g_ctr;                         // work-steal counter

// smem tile geometry
#define APITCH 40
#define BPITCH 136
#define A_BYTES (128 * APITCH * 2)                 // 10240
#define B_BYTES (BK * BPITCH * 2)                  // 8704
#define BUF_BYTES (2 * A_BYTES + 2 * B_BYTES)      // 37888
#define SM_TAB    (2 * BUF_BYTES)                  // 75776
#define SMEM_DYN  (SM_TAB + 2 * JR * 4)            // 79872

// ---------------- PTX helpers -----------------------------------------------
__device__ __forceinline__ uint32_t smem_u32(const void* p) {
    uint32_t a;
    asm("{ .reg .u64 t; cvta.to.shared.u64 t, %1; cvt.u32.u64 %0, t; }"
        : "=r"(a) : "l"(p));
    return a;
}
__device__ __forceinline__ void cpa16(uint32_t dst, const void* src) {
    asm volatile("cp.async.cg.shared.global [%0], [%1], 16;"
                 :: "r"(dst), "l"(src) : "memory");
}
#define CPA_COMMIT() asm volatile("cp.async.commit_group;" ::: "memory")
#define CPA_WAIT0()  asm volatile("cp.async.wait_group 0;" ::: "memory")

__device__ __forceinline__ void ldsm4(uint32_t* r, uint32_t addr) {
    asm volatile("ldmatrix.sync.aligned.m8n8.x4.shared.b16 {%0,%1,%2,%3}, [%4];"
                 : "=r"(r[0]), "=r"(r[1]), "=r"(r[2]), "=r"(r[3]) : "r"(addr));
}
__device__ __forceinline__ void ldsm4t(uint32_t* r, uint32_t addr) {
    asm volatile("ldmatrix.sync.aligned.m8n8.x4.trans.shared.b16 {%0,%1,%2,%3}, [%4];"
                 : "=r"(r[0]), "=r"(r[1]), "=r"(r[2]), "=r"(r[3]) : "r"(addr));
}
__device__ __forceinline__ void mma16816(float* c, const uint32_t* a,
                                         const uint32_t* b) {
    asm volatile("mma.sync.aligned.m16n8k16.row.col.f32.bf16.bf16.f32 "
                 "{%0,%1,%2,%3}, {%4,%5,%6,%7}, {%8,%9}, {%0,%1,%2,%3};"
                 : "+f"(c[0]), "+f"(c[1]), "+f"(c[2]), "+f"(c[3])
                 : "r"(a[0]), "r"(a[1]), "r"(a[2]), "r"(a[3]),
                   "r"(b[0]), "r"(b[1]));
}

// ---------------- K1: h = X @ W + per-node scalars + bf16 hi/lo -------------
__global__ void k_h(const float* __restrict__ x,
                    const float* __restrict__ W,
                    const float* __restrict__ a) {
    int i = blockIdx.x;
    int k = threadIdx.x;

    if (i == 0 && k == 0) g_ctr = 0;   // reset work-steal counter each launch

    __shared__ float xs[D];
    __shared__ float red[D];
    __shared__ float res[3];

    xs[k] = x[i * D + k];
    __syncthreads();

    float acc = 0.f;
#pragma unroll 16
    for (int c = 0; c < D; ++c)
        acc = fmaf(xs[c], W[c * D + k], acc);

    g_h[i * D + k] = acc;
    __nv_bfloat16 hi = __float2bfloat16(acc);
    g_hh[i * D + k] = hi;
    g_hl[i * D + k] = __float2bfloat16(acc - __bfloat162float(hi));

    float vals[3] = {acc, acc * a[k], acc * a[D + k]};
#pragma unroll
    for (int v = 0; v < 3; ++v) {
        red[k] = vals[v];
        __syncthreads();
        for (int st = 64; st > 0; st >>= 1) {
            if (k < st) red[k] += red[k + st];
            __syncthreads();
        }
        if (k == 0) res[v] = red[0];
        __syncthreads();
    }
    if (k == 0) {
        float rs = res[0], s = res[1], d = res[2];
        bool  nz = (rs != 0.0f);
        g_src[i] = s;
        g_Bz[i]  = nz ? __expf(d)        : 0.f;
        g_Cz[i]  = nz ? __expf(0.2f * d) : 0.f;
    }
}

// ---------------- K2: softmax stats + bitmask (max-trick) -------------------
__global__ void k_stats(const int* __restrict__ adj) {
    int row  = blockIdx.x * SROWS + (threadIdx.x >> 5);
    int lane = threadIdx.x & 31;

    float src = g_src[row];
    float ea  = __expf(src);
    float eb  = __expf(0.2f * src);

    float s = 0.f, vm = 0.f;
    int   cnt = 0;
    const int4* arow = (const int4*)(adj + (size_t)row * N);
    unsigned* mrow = g_mask + (size_t)row * (N / 32);

    for (int blk2 = 0; blk2 < N / 256; ++blk2) {
        int4 av0 = arow[blk2 * 64 + lane];
        int4 av1 = arow[blk2 * 64 + 32 + lane];
#pragma unroll
        for (int half = 0; half < 2; ++half) {
            int4 av = half ? av1 : av0;
            int blk = blk2 * 2 + half;
            int j0  = blk * 128 + lane * 4;
            float4 bz = __ldg((const float4*)(g_Bz + j0));
            float4 cz = __ldg((const float4*)(g_Cz + j0));

            unsigned nib = (av.x > 0) | ((av.y > 0) << 1) |
                           ((av.z > 0) << 2) | ((av.w > 0) << 3);
            unsigned v = nib;
            v |= __shfl_down_sync(0xffffffffu, v, 1) << 4;
            v |= __shfl_down_sync(0xffffffffu, v, 2) << 8;
            v |= __shfl_down_sync(0xffffffffu, v, 4) << 16;
            if ((lane & 7) == 0)
                mrow[blk * 4 + (lane >> 3)] = v;

            float ba[4] = {bz.x, bz.y, bz.z, bz.w};
            float ca[4] = {cz.x, cz.y, cz.z, cz.w};
#pragma unroll
            for (int u = 0; u < 4; ++u) {
                float vv  = fmaxf(ea * ba[u], eb * ca[u]);   // exp(leakyrelu)
                bool  bit = (nib >> u) & 1u;
                float val = bit ? vv : 0.f;
                s  += val;
                vm  = fmaxf(vm, val);
                cnt += (bit && vv > 0.f) ? 1 : 0;            // vv>0 <=> nz_j
            }
        }
    }
#pragma unroll
    for (int o = 16; o > 0; o >>= 1) {
        s   += __shfl_xor_sync(0xffffffffu, s, o);
        vm   = fmaxf(vm, __shfl_xor_sync(0xffffffffu, vm, o));
        cnt += __shfl_xor_sync(0xffffffffu, cnt, o);
    }
    if (lane == 0) {
        bool active = (vm > THR * s);
        float eaF = 0.f, ebF = 0.f, T3 = CUDART_INF_F;
        if (active) {
            float F = (float)cnt / s;     // L / S
            eaF = ea * F;
            ebF = eb * F;
            T3  = THR * (float)cnt;       // w >= THR*L  <=>  att >= THR
        }
        g_rowc[row] = make_float4(eaF, ebF, T3, 0.f);
    }
}

// ---------------- K3: persistent work-stealing MMA kernel -------------------
__global__ void __launch_bounds__(256, 2) k_agg() {
    extern __shared__ __align__(16) char sm[];
    __shared__ unsigned s_u;
    uint32_t smb = smem_u32(sm);

    int tid  = threadIdx.x;
    int lane = tid & 31;
    int wid  = tid >> 5;

    float* s_bz = (float*)(sm + SM_TAB);
    float* s_cz = s_bz + JR;

    int gi  = tid >> 1;           // gen row within i-block
    int j16 = (tid & 1) << 4;     // gen 16-j half within BK
    int wm  = (wid & 3) * 32;     // mma warp tile
    int wn  = (wid >> 2) * 64;

    while (true) {
        if (tid == 0) s_u = atomicAdd(&g_ctr, 1u);
        __syncthreads();          // broadcast unit; also fences prior unit's smem reads
        unsigned u = s_u;
        if (u >= NUNITS) break;

        int split  = u >> 6;
        int iblk   = u & 63;
        int ib     = iblk * 128;
        int jstart = split * JR;

        float4 rc = g_rowc[ib + gi];          // {eaF, ebF, T3}
        const unsigned* mrow =
            g_mask + (size_t)(ib + gi) * (N / 32) + (jstart >> 5);

        float acc[2][8][4];
#pragma unroll
        for (int mf = 0; mf < 2; ++mf)
#pragma unroll
            for (int nf = 0; nf < 8; ++nf)
#pragma unroll
                for (int q = 0; q < 4; ++q) acc[mf][nf][q] = 0.f;

        auto loadB = [&](int t) {
            int b  = t & 1;
            int jb = jstart + t * BK;
            uint32_t Bh = smb + b * BUF_BYTES + 2 * A_BYTES;
            uint32_t Bl = Bh + B_BYTES;
#pragma unroll
            for (int q = 0; q < 2; ++q) {
                int idx = tid + q * 256;
                int r = idx >> 4, g = idx & 15;
                uint32_t doff = (uint32_t)(r * BPITCH + g * 8) * 2;
                cpa16(Bh + doff, g_hh + (size_t)(jb + r) * D + g * 8);
                cpa16(Bl + doff, g_hl + (size_t)(jb + r) * D + g * 8);
            }
            CPA_COMMIT();
        };

        auto gen_store = [&](int t, unsigned mw_full) {
            int b = t & 1;
            char* Ah = sm + b * BUF_BYTES;
            char* Al = Ah + A_BYTES;
            unsigned mw = mw_full >> j16;
            int lj = t * BK + j16;
            const float4* tb = (const float4*)(s_bz + lj);
            const float4* tc = (const float4*)(s_cz + lj);
            uint32_t* ah32 = (uint32_t*)Ah + gi * (APITCH / 2) + (j16 >> 1);
            uint32_t* al32 = (uint32_t*)Al + gi * (APITCH / 2) + (j16 >> 1);
#pragma unroll
            for (int e = 0; e < 4; ++e) {
                float4 bz = tb[e];
                float4 cz = tc[e];
                float ba[4] = {bz.x, bz.y, bz.z, bz.w};
                float ca[4] = {cz.x, cz.y, cz.z, cz.w};
                float w[4];
#pragma unroll
                for (int k = 0; k < 4; ++k) {
                    float v  = fmaxf(rc.x * ba[k], rc.y * ca[k]);
                    bool  ok = (v >= rc.z) && ((mw >> (e * 4 + k)) & 1u);
                    w[k] = ok ? v : 0.f;
                }
                uint32_t b0 = __float_as_uint(w[0]);
                uint32_t b1 = __float_as_uint(w[1]);
                uint32_t b2 = __float_as_uint(w[2]);
                uint32_t b3 = __float_as_uint(w[3]);
                uint32_t hp0 = __byte_perm(b0, b1, 0x7632);   // {hi16(w1),hi16(w0)}
                uint32_t hp1 = __byte_perm(b2, b3, 0x7632);
                float lo0 = w[0] - __uint_as_float(b0 & 0xffff0000u);
                float lo1 = w[1] - __uint_as_float(b1 & 0xffff0000u);
                float lo2 = w[2] - __uint_as_float(b2 & 0xffff0000u);
                float lo3 = w[3] - __uint_as_float(b3 & 0xffff0000u);
                uint32_t lp0, lp1;
                asm("cvt.rn.bf16x2.f32 %0, %1, %2;" : "=r"(lp0) : "f"(lo1), "f"(lo0));
                asm("cvt.rn.bf16x2.f32 %0, %1, %2;" : "=r"(lp1) : "f"(lo3), "f"(lo2));
                *(uint2*)&ah32[e * 2] = make_uint2(hp0, hp1);
                *(uint2*)&al32[e * 2] = make_uint2(lp0, lp1);
            }
        };

        auto domma = [&](int t) {
            int b = t & 1;
            uint32_t Ah = smb + b * BUF_BYTES;
            uint32_t Al = Ah + A_BYTES;
            uint32_t Bh = Ah + 2 * A_BYTES;
            uint32_t Bl = Bh + B_BYTES;
#pragma unroll
            for (int ks = 0; ks < 2; ++ks) {
                int k0 = ks * 16;
                uint32_t ahf[2][4], alf[2][4];
#pragma unroll
                for (int mf = 0; mf < 2; ++mf) {
                    uint32_t row = wm + mf * 16 + (lane & 15);
                    uint32_t off = row * (APITCH * 2) + (k0 + ((lane >> 4) << 3)) * 2;
                    ldsm4(ahf[mf], Ah + off);
                    ldsm4(alf[mf], Al + off);
                }
#pragma unroll
                for (int nf2 = 0; nf2 < 4; ++nf2) {
                    int n0 = wn + nf2 * 16;
                    uint32_t r = k0 + (lane & 7) + ((lane >> 3) & 1) * 8;
                    uint32_t c = n0 + ((lane >> 4) << 3);
                    uint32_t off = r * (BPITCH * 2) + c * 2;
                    uint32_t bh[4], bl[4];
                    ldsm4t(bh, Bh + off);
                    ldsm4t(bl, Bl + off);
#pragma unroll
                    for (int mf = 0; mf < 2; ++mf) {
                        mma16816(acc[mf][nf2 * 2],     ahf[mf], bh);
                        mma16816(acc[mf][nf2 * 2],     ahf[mf], bl);
                        mma16816(acc[mf][nf2 * 2],     alf[mf], bh);
                        mma16816(acc[mf][nf2 * 2 + 1], ahf[mf], bh + 2);
                        mma16816(acc[mf][nf2 * 2 + 1], ahf[mf], bl + 2);
                        mma16816(acc[mf][nf2 * 2 + 1], alf[mf], bh + 2);
                    }
                }
            }
        };

        // ---- unit prologue: stage tables + B(0) ----------------------------
        loadB(0);
        if (tid < 128)
            ((float4*)s_bz)[tid] = __ldg((const float4*)(g_Bz + jstart) + tid);
        else
            ((float4*)s_cz)[tid - 128] =
                __ldg((const float4*)(g_Cz + jstart) + (tid - 128));
        __syncthreads();
        gen_store(0, __ldg(&mrow[0]));

        // ---- pipeline -------------------------------------------------------
        for (int t = 0; t < NT; ++t) {
            CPA_WAIT0();
            __syncthreads();
            unsigned mwn = 0;
            if (t + 1 < NT) {
                mwn = __ldg(&mrow[t + 1]);
                loadB(t + 1);
            }
            domma(t);
            if (t + 1 < NT) gen_store(t + 1, mwn);
        }

        // ---- epilogue: write split partial ----------------------------------
        int r0    = ib + wm + (lane >> 2);
        int cbase = wn + (lane & 3) * 2;
#pragma unroll
        for (int mf = 0; mf < 2; ++mf)
#pragma unroll
            for (int nf = 0; nf < 8; ++nf) {
                int row = r0 + mf * 16;
                int col = cbase + nf * 8;
                float* p = &g_part[split][(size_t)row * D + col];
                *(float2*)p           = make_float2(acc[mf][nf][0], acc[mf][nf][1]);
                *(float2*)(p + 8 * D) = make_float2(acc[mf][nf][2], acc[mf][nf][3]);
            }
    }
}

// ---------------- K4: combine partials + residual + ELU ---------------------
__global__ void k_out(float* __restrict__ out) {
    int g = blockIdx.x * blockDim.x + threadIdx.x;
    float4 v = ((const float4*)g_h)[g];
#pragma unroll
    for (int s = 0; s < SPLIT; ++s) {
        float4 p = __ldg((const float4*)g_part[s] + g);
        v.x += p.x; v.y += p.y; v.z += p.z; v.w += p.w;
    }
    float4 o;
    o.x = (v.x > 0.f) ? v.x : expm1f(v.x);
    o.y = (v.y > 0.f) ? v.y : expm1f(v.y);
    o.z = (v.z > 0.f) ? v.z : expm1f(v.z);
    o.w = (v.w > 0.f) ? v.w : expm1f(v.w);
    ((float4*)out)[g] = o;
}

// ---------------- launch ----------------------------------------------------
extern "C" void kernel_launch(void* const* d_in, const int* in_sizes, int n_in,
                              void* d_out, int out_size) {
    (void)in_sizes; (void)n_in; (void)out_size;
    const float* x   = (const float*)d_in[0];
    const float* W   = (const float*)d_in[1];
    const float* a   = (const float*)d_in[2];
    const int*   adj = (const int*)d_in[3];
    float*       out = (float*)d_out;

    cudaFuncSetAttribute(k_agg, cudaFuncAttributeMaxDynamicSharedMemorySize, SMEM_DYN);

    k_h    <<<N, 128>>>(x, W, a);
    k_stats<<<N / SROWS, 256>>>(adj);
    k_agg  <<<NCTA, 256, SMEM_DYN>>>();
    k_out  <<<(N * D) / 1024, 256>>>(out);
}

// round 10
// speedup vs baseline: 3.7094x; 1.0317x over previous
#include <cuda_runtime.h>
#include <cuda_bf16.h>
#include <math_constants.h>
#include <cstdint>

#define N      8192
#define D      128
#define THR    1e-4f
#define SPLIT  16
#define BK     32
#define JR     (N / SPLIT)          // 512 j per unit
#define NT     (JR / BK)            // 16 K-iterations per unit
#define MB     64                   // i-rows per unit (M tile)
#define NIB    (N / MB)             // 128 i-blocks
#define NUNITS (NIB * SPLIT)        // 2048 work units
#define NCTA   444                  // 148 SMs x 3
#define SROWS  8

// ---------------- scratch (static device globals; no allocation) ------------
__device__ float    g_h[N * D];                    // 4 MB fp32 h (residual)
__device__ float    g_src[N], g_Bz[N], g_Cz[N];
__device__ float4   g_rowc[N];                     // {eaF, ebF, T3, -}
__device__ unsigned g_mask[(size_t)N * N / 32];    // 8 MB adjacency bits
__device__ __align__(16) __nv_bfloat16 g_hh[N * D];  // 2 MB h hi
__device__ __align__(16) __nv_bfloat16 g_hl[N * D];  // 2 MB h lo
__device__ float    g_part[SPLIT][N * D];          // 64 MB split-K partials
__device__ unsigned g_ctr;                         // work-steal counter

// smem tile geometry
#define APITCH 40
#define BPITCH 136
#define A_BYTES (MB * APITCH * 2)                  // 5120
#define B_BYTES (BK * BPITCH * 2)                  // 8704
#define BUF_BYTES (2 * A_BYTES + 2 * B_BYTES)      // 27648
#define SM_TAB    (2 * BUF_BYTES)                  // 55296
#define SMEM_DYN  (SM_TAB + 2 * JR * 4)            // 59392 -> 3 CTAs/SM

// ---------------- PTX helpers -----------------------------------------------
__device__ __forceinline__ uint32_t smem_u32(const void* p) {
    uint32_t a;
    asm("{ .reg .u64 t; cvta.to.shared.u64 t, %1; cvt.u32.u64 %0, t; }"
        : "=r"(a) : "l"(p));
    return a;
}
__device__ __forceinline__ void cpa16(uint32_t dst, const void* src) {
    asm volatile("cp.async.cg.shared.global [%0], [%1], 16;"
                 :: "r"(dst), "l"(src) : "memory");
}
#define CPA_COMMIT() asm volatile("cp.async.commit_group;" ::: "memory")
#define CPA_WAIT0()  asm volatile("cp.async.wait_group 0;" ::: "memory")

__device__ __forceinline__ void ldsm4(uint32_t* r, uint32_t addr) {
    asm volatile("ldmatrix.sync.aligned.m8n8.x4.shared.b16 {%0,%1,%2,%3}, [%4];"
                 : "=r"(r[0]), "=r"(r[1]), "=r"(r[2]), "=r"(r[3]) : "r"(addr));
}
__device__ __forceinline__ void ldsm4t(uint32_t* r, uint32_t addr) {
    asm volatile("ldmatrix.sync.aligned.m8n8.x4.trans.shared.b16 {%0,%1,%2,%3}, [%4];"
                 : "=r"(r[0]), "=r"(r[1]), "=r"(r[2]), "=r"(r[3]) : "r"(addr));
}
__device__ __forceinline__ void mma16816(float* c, const uint32_t* a,
                                         const uint32_t* b) {
    asm volatile("mma.sync.aligned.m16n8k16.row.col.f32.bf16.bf16.f32 "
                 "{%0,%1,%2,%3}, {%4,%5,%6,%7}, {%8,%9}, {%0,%1,%2,%3};"
                 : "+f"(c[0]), "+f"(c[1]), "+f"(c[2]), "+f"(c[3])
                 : "r"(a[0]), "r"(a[1]), "r"(a[2]), "r"(a[3]),
                   "r"(b[0]), "r"(b[1]));
}

// ---------------- K1: h = X @ W + per-node scalars + bf16 hi/lo -------------
__global__ void k_h(const float* __restrict__ x,
                    const float* __restrict__ W,
                    const float* __restrict__ a) {
    int i = blockIdx.x;
    int k = threadIdx.x;

    if (i == 0 && k == 0) g_ctr = 0;

    __shared__ float xs[D];
    __shared__ float red[D];
    __shared__ float res[3];

    xs[k] = x[i * D + k];
    __syncthreads();

    float acc = 0.f;
#pragma unroll 16
    for (int c = 0; c < D; ++c)
        acc = fmaf(xs[c], W[c * D + k], acc);

    g_h[i * D + k] = acc;
    __nv_bfloat16 hi = __float2bfloat16(acc);
    g_hh[i * D + k] = hi;
    g_hl[i * D + k] = __float2bfloat16(acc - __bfloat162float(hi));

    float vals[3] = {acc, acc * a[k], acc * a[D + k]};
#pragma unroll
    for (int v = 0; v < 3; ++v) {
        red[k] = vals[v];
        __syncthreads();
        for (int st = 64; st > 0; st >>= 1) {
            if (k < st) red[k] += red[k + st];
            __syncthreads();
        }
        if (k == 0) res[v] = red[0];
        __syncthreads();
    }
    if (k == 0) {
        float rs = res[0], s = res[1], d = res[2];
        bool  nz = (rs != 0.0f);
        g_src[i] = s;
        g_Bz[i]  = nz ? __expf(d)        : 0.f;
        g_Cz[i]  = nz ? __expf(0.2f * d) : 0.f;
    }
}

// ---------------- K2: softmax stats + bitmask (MLP=4) -----------------------
__global__ void k_stats(const int* __restrict__ adj) {
    int row  = blockIdx.x * SROWS + (threadIdx.x >> 5);
    int lane = threadIdx.x & 31;

    float src = g_src[row];
    float ea  = __expf(src);
    float eb  = __expf(0.2f * src);

    float s = 0.f, vm = 0.f;
    int   cnt = 0;
    const int4* arow = (const int4*)(adj + (size_t)row * N);
    unsigned* mrow = g_mask + (size_t)row * (N / 32);

    for (int blk4 = 0; blk4 < N / 512; ++blk4) {
        int4 av[4];
#pragma unroll
        for (int q = 0; q < 4; ++q)
            av[q] = arow[blk4 * 128 + q * 32 + lane];   // 4 loads in flight
#pragma unroll
        for (int q = 0; q < 4; ++q) {
            int blk = blk4 * 4 + q;
            int j0  = blk * 128 + lane * 4;
            float4 bz = __ldg((const float4*)(g_Bz + j0));
            float4 cz = __ldg((const float4*)(g_Cz + j0));

            unsigned nib = (av[q].x > 0) | ((av[q].y > 0) << 1) |
                           ((av[q].z > 0) << 2) | ((av[q].w > 0) << 3);
            unsigned v = nib;
            v |= __shfl_down_sync(0xffffffffu, v, 1) << 4;
            v |= __shfl_down_sync(0xffffffffu, v, 2) << 8;
            v |= __shfl_down_sync(0xffffffffu, v, 4) << 16;
            if ((lane & 7) == 0)
                mrow[blk * 4 + (lane >> 3)] = v;

            float ba[4] = {bz.x, bz.y, bz.z, bz.w};
            float ca[4] = {cz.x, cz.y, cz.z, cz.w};
#pragma unroll
            for (int u = 0; u < 4; ++u) {
                float vv  = fmaxf(ea * ba[u], eb * ca[u]);
                bool  bit = (nib >> u) & 1u;
                float val = bit ? vv : 0.f;
                s  += val;
                vm  = fmaxf(vm, val);
                cnt += (bit && vv > 0.f) ? 1 : 0;
            }
        }
    }
#pragma unroll
    for (int o = 16; o > 0; o >>= 1) {
        s   += __shfl_xor_sync(0xffffffffu, s, o);
        vm   = fmaxf(vm, __shfl_xor_sync(0xffffffffu, vm, o));
        cnt += __shfl_xor_sync(0xffffffffu, cnt, o);
    }
    if (lane == 0) {
        bool active = (vm > THR * s);
        float eaF = 0.f, ebF = 0.f, T3 = CUDART_INF_F;
        if (active) {
            float F = (float)cnt / s;
            eaF = ea * F;
            ebF = eb * F;
            T3  = THR * (float)cnt;
        }
        g_rowc[row] = make_float4(eaF, ebF, T3, 0.f);
    }
}

// ---------------- K3: persistent work-stealing MMA kernel (M=64, occ 3) -----
__global__ void __launch_bounds__(256, 3) k_agg() {
    extern __shared__ __align__(16) char sm[];
    __shared__ unsigned s_u;
    uint32_t smb = smem_u32(sm);

    int tid  = threadIdx.x;
    int lane = tid & 31;
    int wid  = tid >> 5;

    float* s_bz = (float*)(sm + SM_TAB);
    float* s_cz = s_bz + JR;

    int gi = tid >> 2;            // gen row within i-block (0..63)
    int j8 = (tid & 3) << 3;      // gen 8-j slice within BK
    int wm = (wid & 1) * 32;      // mma warp tile: 2 x 4 grid of 32x32
    int wn = (wid >> 1) * 32;

    while (true) {
        if (tid == 0) s_u = atomicAdd(&g_ctr, 1u);
        __syncthreads();
        unsigned u = s_u;
        if (u >= NUNITS) break;

        int split  = u >> 7;          // 0..15
        int iblk   = u & 127;
        int ib     = iblk * MB;
        int jstart = split * JR;

        float4 rc = g_rowc[ib + gi];
        const unsigned* mrow =
            g_mask + (size_t)(ib + gi) * (N / 32) + (jstart >> 5);

        float acc[2][4][4];
#pragma unroll
        for (int mf = 0; mf < 2; ++mf)
#pragma unroll
            for (int nf = 0; nf < 4; ++nf)
#pragma unroll
                for (int q = 0; q < 4; ++q) acc[mf][nf][q] = 0.f;

        auto loadB = [&](int t) {
            int b  = t & 1;
            int jb = jstart + t * BK;
            uint32_t Bh = smb + b * BUF_BYTES + 2 * A_BYTES;
            uint32_t Bl = Bh + B_BYTES;
#pragma unroll
            for (int q = 0; q < 2; ++q) {
                int idx = tid + q * 256;
                int r = idx >> 4, g = idx & 15;
                uint32_t doff = (uint32_t)(r * BPITCH + g * 8) * 2;
                cpa16(Bh + doff, g_hh + (size_t)(jb + r) * D + g * 8);
                cpa16(Bl + doff, g_hl + (size_t)(jb + r) * D + g * 8);
            }
            CPA_COMMIT();
        };

        auto gen_store = [&](int t, unsigned mw_full) {
            int b = t & 1;
            char* Ah = sm + b * BUF_BYTES;
            char* Al = Ah + A_BYTES;
            unsigned mw = mw_full >> j8;
            int lj = t * BK + j8;
            const float4* tb = (const float4*)(s_bz + lj);
            const float4* tc = (const float4*)(s_cz + lj);
            uint32_t* ah32 = (uint32_t*)Ah + gi * (APITCH / 2) + (j8 >> 1);
            uint32_t* al32 = (uint32_t*)Al + gi * (APITCH / 2) + (j8 >> 1);
#pragma unroll
            for (int e = 0; e < 2; ++e) {
                float4 bz = tb[e];
                float4 cz = tc[e];
                float ba[4] = {bz.x, bz.y, bz.z, bz.w};
                float ca[4] = {cz.x, cz.y, cz.z, cz.w};
                float w[4];
#pragma unroll
                for (int k = 0; k < 4; ++k) {
                    float v  = fmaxf(rc.x * ba[k], rc.y * ca[k]);
                    bool  ok = (v >= rc.z) && ((mw >> (e * 4 + k)) & 1u);
                    w[k] = ok ? v : 0.f;
                }
                uint32_t b0 = __float_as_uint(w[0]);
                uint32_t b1 = __float_as_uint(w[1]);
                uint32_t b2 = __float_as_uint(w[2]);
                uint32_t b3 = __float_as_uint(w[3]);
                uint32_t hp0 = __byte_perm(b0, b1, 0x7632);
                uint32_t hp1 = __byte_perm(b2, b3, 0x7632);
                float lo0 = w[0] - __uint_as_float(b0 & 0xffff0000u);
                float lo1 = w[1] - __uint_as_float(b1 & 0xffff0000u);
                float lo2 = w[2] - __uint_as_float(b2 & 0xffff0000u);
                float lo3 = w[3] - __uint_as_float(b3 & 0xffff0000u);
                uint32_t lp0, lp1;
                asm("cvt.rn.bf16x2.f32 %0, %1, %2;" : "=r"(lp0) : "f"(lo1), "f"(lo0));
                asm("cvt.rn.bf16x2.f32 %0, %1, %2;" : "=r"(lp1) : "f"(lo3), "f"(lo2));
                *(uint2*)&ah32[e * 2] = make_uint2(hp0, hp1);
                *(uint2*)&al32[e * 2] = make_uint2(lp0, lp1);
            }
        };

        auto domma = [&](int t) {
            int b = t & 1;
            uint32_t Ah = smb + b * BUF_BYTES;
            uint32_t Al = Ah + A_BYTES;
            uint32_t Bh = Ah + 2 * A_BYTES;
            uint32_t Bl = Bh + B_BYTES;
#pragma unroll
            for (int ks = 0; ks < 2; ++ks) {
                int k0 = ks * 16;
                uint32_t ahf[2][4], alf[2][4];
#pragma unroll
                for (int mf = 0; mf < 2; ++mf) {
                    uint32_t row = wm + mf * 16 + (lane & 15);
                    uint32_t off = row * (APITCH * 2) + (k0 + ((lane >> 4) << 3)) * 2;
                    ldsm4(ahf[mf], Ah + off);
                    ldsm4(alf[mf], Al + off);
                }
#pragma unroll
                for (int nf2 = 0; nf2 < 2; ++nf2) {
                    int n0 = wn + nf2 * 16;
                    uint32_t r = k0 + (lane & 7) + ((lane >> 3) & 1) * 8;
                    uint32_t c = n0 + ((lane >> 4) << 3);
                    uint32_t off = r * (BPITCH * 2) + c * 2;
                    uint32_t bh[4], bl[4];
                    ldsm4t(bh, Bh + off);
                    ldsm4t(bl, Bl + off);
#pragma unroll
                    for (int mf = 0; mf < 2; ++mf) {
                        mma16816(acc[mf][nf2 * 2],     ahf[mf], bh);
                        mma16816(acc[mf][nf2 * 2],     ahf[mf], bl);
                        mma16816(acc[mf][nf2 * 2],     alf[mf], bh);
                        mma16816(acc[mf][nf2 * 2 + 1], ahf[mf], bh + 2);
                        mma16816(acc[mf][nf2 * 2 + 1], ahf[mf], bl + 2);
                        mma16816(acc[mf][nf2 * 2 + 1], alf[mf], bh + 2);
                    }
                }
            }
        };

        // ---- unit prologue ---------------------------------------------------
        loadB(0);
        if (tid < 128)
            ((float4*)s_bz)[tid] = __ldg((const float4*)(g_Bz + jstart) + tid);
        else
            ((float4*)s_cz)[tid - 128] =
                __ldg((const float4*)(g_Cz + jstart) + (tid - 128));
        __syncthreads();
        gen_store(0, __ldg(&mrow[0]));

        // ---- pipeline --------------------------------------------------------
        for (int t = 0; t < NT; ++t) {
            CPA_WAIT0();
            __syncthreads();
            unsigned mwn = 0;
            if (t + 1 < NT) {
                mwn = __ldg(&mrow[t + 1]);
                loadB(t + 1);
            }
            domma(t);
            if (t + 1 < NT) gen_store(t + 1, mwn);
        }

        // ---- epilogue: write split partial -----------------------------------
        int r0    = ib + wm + (lane >> 2);
        int cbase = wn + (lane & 3) * 2;
#pragma unroll
        for (int mf = 0; mf < 2; ++mf)
#pragma unroll
            for (int nf = 0; nf < 4; ++nf) {
                int row = r0 + mf * 16;
                int col = cbase + nf * 8;
                float* p = &g_part[split][(size_t)row * D + col];
                *(float2*)p           = make_float2(acc[mf][nf][0], acc[mf][nf][1]);
                *(float2*)(p + 8 * D) = make_float2(acc[mf][nf][2], acc[mf][nf][3]);
            }
    }
}

// ---------------- K4: combine partials + residual + ELU ---------------------
__global__ void k_out(float* __restrict__ out) {
    int g = blockIdx.x * blockDim.x + threadIdx.x;
    float4 v = ((const float4*)g_h)[g];
#pragma unroll
    for (int s = 0; s < SPLIT; ++s) {
        float4 p = __ldg((const float4*)g_part[s] + g);
        v.x += p.x; v.y += p.y; v.z += p.z; v.w += p.w;
    }
    float4 o;
    o.x = (v.x > 0.f) ? v.x : expm1f(v.x);
    o.y = (v.y > 0.f) ? v.y : expm1f(v.y);
    o.z = (v.z > 0.f) ? v.z : expm1f(v.z);
    o.w = (v.w > 0.f) ? v.w : expm1f(v.w);
    ((float4*)out)[g] = o;
}

// ---------------- launch ----------------------------------------------------
extern "C" void kernel_launch(void* const* d_in, const int* in_sizes, int n_in,
                              void* d_out, int out_size) {
    (void)in_sizes; (void)n_in; (void)out_size;
    const float* x   = (const float*)d_in[0];
    const float* W   = (const float*)d_in[1];
    const float* a   = (const float*)d_in[2];
    const int*   adj = (const int*)d_in[3];
    float*       out = (float*)d_out;

    cudaFuncSetAttribute(k_agg, cudaFuncAttributeMaxDynamicSharedMemorySize, SMEM_DYN);

    k_h    <<<N, 128>>>(x, W, a);
    k_stats<<<N / SROWS, 256>>>(adj);
    k_agg  <<<NCTA, 256, SMEM_DYN>>>();
    k_out  <<<(N * D) / 1024, 256>>>(out);
}

// round 11
// speedup vs baseline: 4.3356x; 1.1688x over previous
#include <cuda_runtime.h>
#include <cuda_fp16.h>
#include <math_constants.h>
#include <cstdint>

#define N      8192
#define D      128
#define THR    1e-4f
#define SPLIT  16
#define BK     32
#define JR     (N / SPLIT)          // 512 j per unit
#define NT     (JR / BK)            // 16 K-iterations per unit
#define MB     64                   // i-rows per unit
#define NIB    (N / MB)             // 128 i-blocks
#define NUNITS (NIB * SPLIT)        // 2048 work units
#define NCTA   444                  // 148 SMs x 3
#define SROWS  8

// ---------------- scratch (static device globals; no allocation) ------------
__device__ float    g_h[N * D];                    // 4 MB fp32 h (residual)
__device__ float    g_src[N], g_Bz[N], g_Cz[N];
__device__ float4   g_rowc[N];                     // {eaF, ebF, T3, -}
__device__ unsigned g_mask[(size_t)N * N / 32];    // 8 MB adjacency bits
__device__ __align__(16) __half g_hh[N * D];       // 2 MB h hi (fp16)
__device__ __align__(16) __half g_hl[N * D];       // 2 MB h lo (fp16)
__device__ float    g_part[SPLIT][N * D];          // 64 MB split-K partials
__device__ unsigned g_ctr;                         // work-steal counter

// smem tile geometry (16-bit pitches; odd 16B-granule counts -> LDSM conflict-free)
#define APITCH 40
#define BPITCH 136
#define A_BYTES (MB * APITCH * 2)                  // 5120  (single A buffer now)
#define B_BYTES (BK * BPITCH * 2)                  // 8704
#define BUF_BYTES (A_BYTES + 2 * B_BYTES)          // 22528
#define SM_TAB    (2 * BUF_BYTES)                  // 45056
#define SMEM_DYN  (SM_TAB + 2 * JR * 4)            // 49152 -> 3 CTAs/SM easily

// ---------------- PTX helpers -----------------------------------------------
__device__ __forceinline__ uint32_t smem_u32(const void* p) {
    uint32_t a;
    asm("{ .reg .u64 t; cvta.to.shared.u64 t, %1; cvt.u32.u64 %0, t; }"
        : "=r"(a) : "l"(p));
    return a;
}
__device__ __forceinline__ void cpa16(uint32_t dst, const void* src) {
    asm volatile("cp.async.cg.shared.global [%0], [%1], 16;"
                 :: "r"(dst), "l"(src) : "memory");
}
#define CPA_COMMIT() asm volatile("cp.async.commit_group;" ::: "memory")
#define CPA_WAIT0()  asm volatile("cp.async.wait_group 0;" ::: "memory")

__device__ __forceinline__ void ldsm4(uint32_t* r, uint32_t addr) {
    asm volatile("ldmatrix.sync.aligned.m8n8.x4.shared.b16 {%0,%1,%2,%3}, [%4];"
                 : "=r"(r[0]), "=r"(r[1]), "=r"(r[2]), "=r"(r[3]) : "r"(addr));
}
__device__ __forceinline__ void ldsm4t(uint32_t* r, uint32_t addr) {
    asm volatile("ldmatrix.sync.aligned.m8n8.x4.trans.shared.b16 {%0,%1,%2,%3}, [%4];"
                 : "=r"(r[0]), "=r"(r[1]), "=r"(r[2]), "=r"(r[3]) : "r"(addr));
}
__device__ __forceinline__ void mma16816(float* c, const uint32_t* a,
                                         const uint32_t* b) {
    asm volatile("mma.sync.aligned.m16n8k16.row.col.f32.f16.f16.f32 "
                 "{%0,%1,%2,%3}, {%4,%5,%6,%7}, {%8,%9}, {%0,%1,%2,%3};"
                 : "+f"(c[0]), "+f"(c[1]), "+f"(c[2]), "+f"(c[3])
                 : "r"(a[0]), "r"(a[1]), "r"(a[2]), "r"(a[3]),
                   "r"(b[0]), "r"(b[1]));
}

// ---------------- K1: h = X @ W + per-node scalars + fp16 hi/lo -------------
__global__ void k_h(const float* __restrict__ x,
                    const float* __restrict__ W,
                    const float* __restrict__ a) {
    int i = blockIdx.x;
    int k = threadIdx.x;

    if (i == 0 && k == 0) g_ctr = 0;

    __shared__ float xs[D];
    __shared__ float red[D];
    __shared__ float res[3];

    xs[k] = x[i * D + k];
    __syncthreads();

    float acc = 0.f;
#pragma unroll 16
    for (int c = 0; c < D; ++c)
        acc = fmaf(xs[c], W[c * D + k], acc);

    g_h[i * D + k] = acc;
    __half hi = __float2half_rn(acc);
    g_hh[i * D + k] = hi;
    g_hl[i * D + k] = __float2half_rn(acc - __half2float(hi));

    float vals[3] = {acc, acc * a[k], acc * a[D + k]};
#pragma unroll
    for (int v = 0; v < 3; ++v) {
        red[k] = vals[v];
        __syncthreads();
        for (int st = 64; st > 0; st >>= 1) {
            if (k < st) red[k] += red[k + st];
            __syncthreads();
        }
        if (k == 0) res[v] = red[0];
        __syncthreads();
    }
    if (k == 0) {
        float rs = res[0], s = res[1], d = res[2];
        bool  nz = (rs != 0.0f);
        g_src[i] = s;
        g_Bz[i]  = nz ? __expf(d)        : 0.f;
        g_Cz[i]  = nz ? __expf(0.2f * d) : 0.f;
    }
}

// ---------------- K2: softmax stats + bitmask (MLP=4) -----------------------
__global__ void k_stats(const int* __restrict__ adj) {
    int row  = blockIdx.x * SROWS + (threadIdx.x >> 5);
    int lane = threadIdx.x & 31;

    float src = g_src[row];
    float ea  = __expf(src);
    float eb  = __expf(0.2f * src);

    float s = 0.f, vm = 0.f;
    int   cnt = 0;
    const int4* arow = (const int4*)(adj + (size_t)row * N);
    unsigned* mrow = g_mask + (size_t)row * (N / 32);

    for (int blk4 = 0; blk4 < N / 512; ++blk4) {
        int4 av[4];
#pragma unroll
        for (int q = 0; q < 4; ++q)
            av[q] = arow[blk4 * 128 + q * 32 + lane];
#pragma unroll
        for (int q = 0; q < 4; ++q) {
            int blk = blk4 * 4 + q;
            int j0  = blk * 128 + lane * 4;
            float4 bz = __ldg((const float4*)(g_Bz + j0));
            float4 cz = __ldg((const float4*)(g_Cz + j0));

            unsigned nib = (av[q].x > 0) | ((av[q].y > 0) << 1) |
                           ((av[q].z > 0) << 2) | ((av[q].w > 0) << 3);
            unsigned v = nib;
            v |= __shfl_down_sync(0xffffffffu, v, 1) << 4;
            v |= __shfl_down_sync(0xffffffffu, v, 2) << 8;
            v |= __shfl_down_sync(0xffffffffu, v, 4) << 16;
            if ((lane & 7) == 0)
                mrow[blk * 4 + (lane >> 3)] = v;

            float ba[4] = {bz.x, bz.y, bz.z, bz.w};
            float ca[4] = {cz.x, cz.y, cz.z, cz.w};
#pragma unroll
            for (int u = 0; u < 4; ++u) {
                float vv  = fmaxf(ea * ba[u], eb * ca[u]);
                bool  bit = (nib >> u) & 1u;
                float val = bit ? vv : 0.f;
                s  += val;
                vm  = fmaxf(vm, val);
                cnt += (bit && vv > 0.f) ? 1 : 0;
            }
        }
    }
#pragma unroll
    for (int o = 16; o > 0; o >>= 1) {
        s   += __shfl_xor_sync(0xffffffffu, s, o);
        vm   = fmaxf(vm, __shfl_xor_sync(0xffffffffu, vm, o));
        cnt += __shfl_xor_sync(0xffffffffu, cnt, o);
    }
    if (lane == 0) {
        bool active = (vm > THR * s);
        float eaF = 0.f, ebF = 0.f, T3 = CUDART_INF_F;
        if (active) {
            float F = (float)cnt / s;
            eaF = ea * F;
            ebF = eb * F;
            T3  = THR * (float)cnt;
        }
        g_rowc[row] = make_float4(eaF, ebF, T3, 0.f);
    }
}

// ---------------- K3: persistent MMA kernel (fp16 2-pass, M=64, occ 3) ------
__global__ void __launch_bounds__(256, 3) k_agg() {
    extern __shared__ __align__(16) char sm[];
    __shared__ unsigned s_u;
    uint32_t smb = smem_u32(sm);

    int tid  = threadIdx.x;
    int lane = tid & 31;
    int wid  = tid >> 5;

    float* s_bz = (float*)(sm + SM_TAB);
    float* s_cz = s_bz + JR;

    int gi = tid >> 2;            // gen row within i-block (0..63)
    int j8 = (tid & 3) << 3;      // gen 8-j slice within BK
    int wm = (wid & 1) * 32;      // mma warp tile: 2 x 4 grid of 32x32
    int wn = (wid >> 1) * 32;

    while (true) {
        if (tid == 0) s_u = atomicAdd(&g_ctr, 1u);
        __syncthreads();
        unsigned u = s_u;
        if (u >= NUNITS) break;

        int split  = u >> 7;
        int iblk   = u & 127;
        int ib     = iblk * MB;
        int jstart = split * JR;

        float4 rc = g_rowc[ib + gi];
        const unsigned* mrow =
            g_mask + (size_t)(ib + gi) * (N / 32) + (jstart >> 5);

        float acc[2][4][4];
#pragma unroll
        for (int mf = 0; mf < 2; ++mf)
#pragma unroll
            for (int nf = 0; nf < 4; ++nf)
#pragma unroll
                for (int q = 0; q < 4; ++q) acc[mf][nf][q] = 0.f;

        auto loadB = [&](int t) {
            int b  = t & 1;
            int jb = jstart + t * BK;
            uint32_t Bh = smb + b * BUF_BYTES + A_BYTES;
            uint32_t Bl = Bh + B_BYTES;
#pragma unroll
            for (int q = 0; q < 2; ++q) {
                int idx = tid + q * 256;
                int r = idx >> 4, g = idx & 15;
                uint32_t doff = (uint32_t)(r * BPITCH + g * 8) * 2;
                cpa16(Bh + doff, g_hh + (size_t)(jb + r) * D + g * 8);
                cpa16(Bl + doff, g_hl + (size_t)(jb + r) * D + g * 8);
            }
            CPA_COMMIT();
        };

        auto gen_store = [&](int t, unsigned mw_full) {
            int b = t & 1;
            char* Ah = sm + b * BUF_BYTES;
            unsigned mw = mw_full >> j8;
            int lj = t * BK + j8;
            const float4* tb = (const float4*)(s_bz + lj);
            const float4* tc = (const float4*)(s_cz + lj);
            uint32_t* a32 = (uint32_t*)Ah + gi * (APITCH / 2) + (j8 >> 1);
#pragma unroll
            for (int e = 0; e < 2; ++e) {
                float4 bz = tb[e];
                float4 cz = tc[e];
                float ba[4] = {bz.x, bz.y, bz.z, bz.w};
                float ca[4] = {cz.x, cz.y, cz.z, cz.w};
                float w[4];
#pragma unroll
                for (int k = 0; k < 4; ++k) {
                    float v  = fmaxf(rc.x * ba[k], rc.y * ca[k]);
                    bool  ok = (v >= rc.z) && ((mw >> (e * 4 + k)) & 1u);
                    w[k] = ok ? v : 0.f;
                }
                uint32_t p0, p1;
                asm("cvt.rn.f16x2.f32 %0, %1, %2;" : "=r"(p0) : "f"(w[1]), "f"(w[0]));
                asm("cvt.rn.f16x2.f32 %0, %1, %2;" : "=r"(p1) : "f"(w[3]), "f"(w[2]));
                *(uint2*)&a32[e * 2] = make_uint2(p0, p1);
            }
        };

        auto domma = [&](int t) {
            int b = t & 1;
            uint32_t Ah = smb + b * BUF_BYTES;
            uint32_t Bh = Ah + A_BYTES;
            uint32_t Bl = Bh + B_BYTES;
#pragma unroll
            for (int ks = 0; ks < 2; ++ks) {
                int k0 = ks * 16;
                uint32_t af[2][4];
#pragma unroll
                for (int mf = 0; mf < 2; ++mf) {
                    uint32_t row = wm + mf * 16 + (lane & 15);
                    uint32_t off = row * (APITCH * 2) + (k0 + ((lane >> 4) << 3)) * 2;
                    ldsm4(af[mf], Ah + off);
                }
#pragma unroll
                for (int nf2 = 0; nf2 < 2; ++nf2) {
                    int n0 = wn + nf2 * 16;
                    uint32_t r = k0 + (lane & 7) + ((lane >> 3) & 1) * 8;
                    uint32_t c = n0 + ((lane >> 4) << 3);
                    uint32_t off = r * (BPITCH * 2) + c * 2;
                    uint32_t bh[4], bl[4];
                    ldsm4t(bh, Bh + off);
                    ldsm4t(bl, Bl + off);
#pragma unroll
                    for (int mf = 0; mf < 2; ++mf) {
                        mma16816(acc[mf][nf2 * 2],     af[mf], bh);
                        mma16816(acc[mf][nf2 * 2],     af[mf], bl);
                        mma16816(acc[mf][nf2 * 2 + 1], af[mf], bh + 2);
                        mma16816(acc[mf][nf2 * 2 + 1], af[mf], bl + 2);
                    }
                }
            }
        };

        // ---- unit prologue ---------------------------------------------------
        loadB(0);
        if (tid < 128)
            ((float4*)s_bz)[tid] = __ldg((const float4*)(g_Bz + jstart) + tid);
        else
            ((float4*)s_cz)[tid - 128] =
                __ldg((const float4*)(g_Cz + jstart) + (tid - 128));
        __syncthreads();
        gen_store(0, __ldg(&mrow[0]));

        // ---- pipeline --------------------------------------------------------
        for (int t = 0; t < NT; ++t) {
            CPA_WAIT0();
            __syncthreads();
            unsigned mwn = 0;
            if (t + 1 < NT) {
                mwn = __ldg(&mrow[t + 1]);
                loadB(t + 1);
            }
            domma(t);
            if (t + 1 < NT) gen_store(t + 1, mwn);
        }

        // ---- epilogue: write split partial -----------------------------------
        int r0    = ib + wm + (lane >> 2);
        int cbase = wn + (lane & 3) * 2;
#pragma unroll
        for (int mf = 0; mf < 2; ++mf)
#pragma unroll
            for (int nf = 0; nf < 4; ++nf) {
                int row = r0 + mf * 16;
                int col = cbase + nf * 8;
                float* p = &g_part[split][(size_t)row * D + col];
                *(float2*)p           = make_float2(acc[mf][nf][0], acc[mf][nf][1]);
                *(float2*)(p + 8 * D) = make_float2(acc[mf][nf][2], acc[mf][nf][3]);
            }
    }
}

// ---------------- K4: combine partials + residual + ELU ---------------------
__global__ void k_out(float* __restrict__ out) {
    int g = blockIdx.x * blockDim.x + threadIdx.x;
    float4 v = ((const float4*)g_h)[g];
#pragma unroll
    for (int s = 0; s < SPLIT; ++s) {
        float4 p = __ldg((const float4*)g_part[s] + g);
        v.x += p.x; v.y += p.y; v.z += p.z; v.w += p.w;
    }
    float4 o;
    o.x = (v.x > 0.f) ? v.x : expm1f(v.x);
    o.y = (v.y > 0.f) ? v.y : expm1f(v.y);
    o.z = (v.z > 0.f) ? v.z : expm1f(v.z);
    o.w = (v.w > 0.f) ? v.w : expm1f(v.w);
    ((float4*)out)[g] = o;
}

// ---------------- launch ----------------------------------------------------
extern "C" void kernel_launch(void* const* d_in, const int* in_sizes, int n_in,
                              void* d_out, int out_size) {
    (void)in_sizes; (void)n_in; (void)out_size;
    const float* x   = (const float*)d_in[0];
    const float* W   = (const float*)d_in[1];
    const float* a   = (const float*)d_in[2];
    const int*   adj = (const int*)d_in[3];
    float*       out = (float*)d_out;

    cudaFuncSetAttribute(k_agg, cudaFuncAttributeMaxDynamicSharedMemorySize, SMEM_DYN);

    k_h    <<<N, 128>>>(x, W, a);
    k_stats<<<N / SROWS, 256>>>(adj);
    k_agg  <<<NCTA, 256, SMEM_DYN>>>();
    k_out  <<<(N * D) / 1024, 256>>>(out);
}

// round 12
// speedup vs baseline: 4.9322x; 1.1376x over previous
#include <cuda_runtime.h>
#include <cuda_fp16.h>
#include <math_constants.h>
#include <cstdint>

#define N      8192
#define D      128
#define THR    1e-4f
#define SPLIT  16
#define BK     32
#define JR     (N / SPLIT)          // 512 j per unit
#define NT     (JR / BK)            // 16 K-iterations per unit
#define MB     64                   // i-rows per unit
#define NIB    (N / MB)             // 128 i-blocks
#define NUNITS (NIB * SPLIT)        // 2048 work units
#define NCTA   444                  // 148 SMs x 3
#define SROWS  8

// ---------------- scratch (static device globals; no allocation) ------------
__device__ float    g_h[N * D];                    // 4 MB fp32 h (residual)
__device__ float    g_src[N], g_Bz[N], g_Cz[N];
__device__ float4   g_rowc[N];                     // {eaF, ebF, T3, -}
__device__ unsigned g_mask[(size_t)N * N / 32];    // 8 MB adjacency bits
__device__ __align__(16) __half g_hh[N * D];       // 2 MB h (fp16)
__device__ float    g_part[SPLIT][N * D];          // 64 MB split-K partials
__device__ unsigned g_ctr;                         // work-steal counter

// smem tile geometry (16-bit pitches; odd 16B-granule counts -> LDSM conflict-free)
#define APITCH 40
#define BPITCH 136
#define A_BYTES (MB * APITCH * 2)                  // 5120
#define B_BYTES (BK * BPITCH * 2)                  // 8704
#define BUF_BYTES (A_BYTES + B_BYTES)              // 13824
#define SM_TAB    (2 * BUF_BYTES)                  // 27648
#define SMEM_DYN  (SM_TAB + 2 * JR * 4)            // 31744 -> 3 CTAs/SM easily

// ---------------- PTX helpers -----------------------------------------------
__device__ __forceinline__ uint32_t smem_u32(const void* p) {
    uint32_t a;
    asm("{ .reg .u64 t; cvta.to.shared.u64 t, %1; cvt.u32.u64 %0, t; }"
        : "=r"(a) : "l"(p));
    return a;
}
__device__ __forceinline__ void cpa16(uint32_t dst, const void* src) {
    asm volatile("cp.async.cg.shared.global [%0], [%1], 16;"
                 :: "r"(dst), "l"(src) : "memory");
}
#define CPA_COMMIT() asm volatile("cp.async.commit_group;" ::: "memory")
#define CPA_WAIT0()  asm volatile("cp.async.wait_group 0;" ::: "memory")

__device__ __forceinline__ void ldsm4(uint32_t* r, uint32_t addr) {
    asm volatile("ldmatrix.sync.aligned.m8n8.x4.shared.b16 {%0,%1,%2,%3}, [%4];"
                 : "=r"(r[0]), "=r"(r[1]), "=r"(r[2]), "=r"(r[3]) : "r"(addr));
}
__device__ __forceinline__ void ldsm4t(uint32_t* r, uint32_t addr) {
    asm volatile("ldmatrix.sync.aligned.m8n8.x4.trans.shared.b16 {%0,%1,%2,%3}, [%4];"
                 : "=r"(r[0]), "=r"(r[1]), "=r"(r[2]), "=r"(r[3]) : "r"(addr));
}
__device__ __forceinline__ void mma16816(float* c, const uint32_t* a,
                                         const uint32_t* b) {
    asm volatile("mma.sync.aligned.m16n8k16.row.col.f32.f16.f16.f32 "
                 "{%0,%1,%2,%3}, {%4,%5,%6,%7}, {%8,%9}, {%0,%1,%2,%3};"
                 : "+f"(c[0]), "+f"(c[1]), "+f"(c[2]), "+f"(c[3])
                 : "r"(a[0]), "r"(a[1]), "r"(a[2]), "r"(a[3]),
                   "r"(b[0]), "r"(b[1]));
}

// ---------------- K1: h = X @ W + per-node scalars + fp16 -------------------
__global__ void k_h(const float* __restrict__ x,
                    const float* __restrict__ W,
                    const float* __restrict__ a) {
    int i = blockIdx.x;
    int k = threadIdx.x;

    if (i == 0 && k == 0) g_ctr = 0;

    __shared__ float xs[D];
    __shared__ float red[D];
    __shared__ float res[3];

    xs[k] = x[i * D + k];
    __syncthreads();

    float acc = 0.f;
#pragma unroll 16
    for (int c = 0; c < D; ++c)
        acc = fmaf(xs[c], W[c * D + k], acc);

    g_h[i * D + k]  = acc;
    g_hh[i * D + k] = __float2half_rn(acc);

    float vals[3] = {acc, acc * a[k], acc * a[D + k]};
#pragma unroll
    for (int v = 0; v < 3; ++v) {
        red[k] = vals[v];
        __syncthreads();
        for (int st = 64; st > 0; st >>= 1) {
            if (k < st) red[k] += red[k + st];
            __syncthreads();
        }
        if (k == 0) res[v] = red[0];
        __syncthreads();
    }
    if (k == 0) {
        float rs = res[0], s = res[1], d = res[2];
        bool  nz = (rs != 0.0f);
        g_src[i] = s;
        g_Bz[i]  = nz ? __expf(d)        : 0.f;
        g_Cz[i]  = nz ? __expf(0.2f * d) : 0.f;
    }
}

// ---------------- K2: softmax stats + bitmask (MLP=4) -----------------------
__global__ void k_stats(const int* __restrict__ adj) {
    int row  = blockIdx.x * SROWS + (threadIdx.x >> 5);
    int lane = threadIdx.x & 31;

    float src = g_src[row];
    float ea  = __expf(src);
    float eb  = __expf(0.2f * src);

    float s = 0.f, vm = 0.f;
    int   cnt = 0;
    const int4* arow = (const int4*)(adj + (size_t)row * N);
    unsigned* mrow = g_mask + (size_t)row * (N / 32);

    for (int blk4 = 0; blk4 < N / 512; ++blk4) {
        int4 av[4];
#pragma unroll
        for (int q = 0; q < 4; ++q)
            av[q] = arow[blk4 * 128 + q * 32 + lane];
#pragma unroll
        for (int q = 0; q < 4; ++q) {
            int blk = blk4 * 4 + q;
            int j0  = blk * 128 + lane * 4;
            float4 bz = __ldg((const float4*)(g_Bz + j0));
            float4 cz = __ldg((const float4*)(g_Cz + j0));

            unsigned nib = (av[q].x > 0) | ((av[q].y > 0) << 1) |
                           ((av[q].z > 0) << 2) | ((av[q].w > 0) << 3);
            unsigned v = nib;
            v |= __shfl_down_sync(0xffffffffu, v, 1) << 4;
            v |= __shfl_down_sync(0xffffffffu, v, 2) << 8;
            v |= __shfl_down_sync(0xffffffffu, v, 4) << 16;
            if ((lane & 7) == 0)
                mrow[blk * 4 + (lane >> 3)] = v;

            float ba[4] = {bz.x, bz.y, bz.z, bz.w};
            float ca[4] = {cz.x, cz.y, cz.z, cz.w};
#pragma unroll
            for (int u = 0; u < 4; ++u) {
                float vv  = fmaxf(ea * ba[u], eb * ca[u]);
                bool  bit = (nib >> u) & 1u;
                float val = bit ? vv : 0.f;
                s  += val;
                vm  = fmaxf(vm, val);
                cnt += (bit && vv > 0.f) ? 1 : 0;
            }
        }
    }
#pragma unroll
    for (int o = 16; o > 0; o >>= 1) {
        s   += __shfl_xor_sync(0xffffffffu, s, o);
        vm   = fmaxf(vm, __shfl_xor_sync(0xffffffffu, vm, o));
        cnt += __shfl_xor_sync(0xffffffffu, cnt, o);
    }
    if (lane == 0) {
        bool active = (vm > THR * s);
        float eaF = 0.f, ebF = 0.f, T3 = CUDART_INF_F;
        if (active) {
            float F = (float)cnt / s;
            eaF = ea * F;
            ebF = eb * F;
            T3  = THR * (float)cnt;
        }
        g_rowc[row] = make_float4(eaF, ebF, T3, 0.f);
    }
}

// ---------------- K3: persistent MMA kernel (fp16 1-pass, M=64, occ 3) ------
__global__ void __launch_bounds__(256, 3) k_agg() {
    extern __shared__ __align__(16) char sm[];
    __shared__ unsigned s_u;
    uint32_t smb = smem_u32(sm);

    int tid  = threadIdx.x;
    int lane = tid & 31;
    int wid  = tid >> 5;

    float* s_bz = (float*)(sm + SM_TAB);
    float* s_cz = s_bz + JR;

    int gi = tid >> 2;            // gen row within i-block (0..63)
    int j8 = (tid & 3) << 3;      // gen 8-j slice within BK
    int wm = (wid & 1) * 32;      // mma warp tile: 2 x 4 grid of 32x32
    int wn = (wid >> 1) * 32;

    while (true) {
        if (tid == 0) s_u = atomicAdd(&g_ctr, 1u);
        __syncthreads();
        unsigned u = s_u;
        if (u >= NUNITS) break;

        int split  = u >> 7;
        int iblk   = u & 127;
        int ib     = iblk * MB;
        int jstart = split * JR;

        float4 rc = g_rowc[ib + gi];
        const unsigned* mrow =
            g_mask + (size_t)(ib + gi) * (N / 32) + (jstart >> 5);

        float acc[2][4][4];
#pragma unroll
        for (int mf = 0; mf < 2; ++mf)
#pragma unroll
            for (int nf = 0; nf < 4; ++nf)
#pragma unroll
                for (int q = 0; q < 4; ++q) acc[mf][nf][q] = 0.f;

        auto loadB = [&](int t) {
            int b  = t & 1;
            int jb = jstart + t * BK;
            uint32_t Bh = smb + b * BUF_BYTES + A_BYTES;
#pragma unroll
            for (int q = 0; q < 2; ++q) {
                int idx = tid + q * 256;
                int r = idx >> 4, g = idx & 15;
                uint32_t doff = (uint32_t)(r * BPITCH + g * 8) * 2;
                cpa16(Bh + doff, g_hh + (size_t)(jb + r) * D + g * 8);
            }
            CPA_COMMIT();
        };

        auto gen_store = [&](int t, unsigned mw_full) {
            int b = t & 1;
            char* Ah = sm + b * BUF_BYTES;
            unsigned mw = mw_full >> j8;
            int lj = t * BK + j8;
            const float4* tb = (const float4*)(s_bz + lj);
            const float4* tc = (const float4*)(s_cz + lj);
            uint32_t* a32 = (uint32_t*)Ah + gi * (APITCH / 2) + (j8 >> 1);
#pragma unroll
            for (int e = 0; e < 2; ++e) {
                float4 bz = tb[e];
                float4 cz = tc[e];
                float ba[4] = {bz.x, bz.y, bz.z, bz.w};
                float ca[4] = {cz.x, cz.y, cz.z, cz.w};
                float w[4];
#pragma unroll
                for (int k = 0; k < 4; ++k) {
                    float v  = fmaxf(rc.x * ba[k], rc.y * ca[k]);
                    bool  ok = (v >= rc.z) && ((mw >> (e * 4 + k)) & 1u);
                    w[k] = ok ? v : 0.f;
                }
                uint32_t p0, p1;
                asm("cvt.rn.f16x2.f32 %0, %1, %2;" : "=r"(p0) : "f"(w[1]), "f"(w[0]));
                asm("cvt.rn.f16x2.f32 %0, %1, %2;" : "=r"(p1) : "f"(w[3]), "f"(w[2]));
                *(uint2*)&a32[e * 2] = make_uint2(p0, p1);
            }
        };

        auto domma = [&](int t) {
            int b = t & 1;
            uint32_t Ah = smb + b * BUF_BYTES;
            uint32_t Bh = Ah + A_BYTES;
#pragma unroll
            for (int ks = 0; ks < 2; ++ks) {
                int k0 = ks * 16;
                uint32_t af[2][4];
#pragma unroll
                for (int mf = 0; mf < 2; ++mf) {
                    uint32_t row = wm + mf * 16 + (lane & 15);
                    uint32_t off = row * (APITCH * 2) + (k0 + ((lane >> 4) << 3)) * 2;
                    ldsm4(af[mf], Ah + off);
                }
#pragma unroll
                for (int nf2 = 0; nf2 < 2; ++nf2) {
                    int n0 = wn + nf2 * 16;
                    uint32_t r = k0 + (lane & 7) + ((lane >> 3) & 1) * 8;
                    uint32_t c = n0 + ((lane >> 4) << 3);
                    uint32_t off = r * (BPITCH * 2) + c * 2;
                    uint32_t bh[4];
                    ldsm4t(bh, Bh + off);
#pragma unroll
                    for (int mf = 0; mf < 2; ++mf) {
                        mma16816(acc[mf][nf2 * 2],     af[mf], bh);
                        mma16816(acc[mf][nf2 * 2 + 1], af[mf], bh + 2);
                    }
                }
            }
        };

        // ---- unit prologue ---------------------------------------------------
        loadB(0);
        if (tid < 128)
            ((float4*)s_bz)[tid] = __ldg((const float4*)(g_Bz + jstart) + tid);
        else
            ((float4*)s_cz)[tid - 128] =
                __ldg((const float4*)(g_Cz + jstart) + (tid - 128));
        __syncthreads();
        gen_store(0, __ldg(&mrow[0]));

        // ---- pipeline --------------------------------------------------------
        for (int t = 0; t < NT; ++t) {
            CPA_WAIT0();
            __syncthreads();
            unsigned mwn = 0;
            if (t + 1 < NT) {
                mwn = __ldg(&mrow[t + 1]);
                loadB(t + 1);
            }
            domma(t);
            if (t + 1 < NT) gen_store(t + 1, mwn);
        }

        // ---- epilogue: write split partial -----------------------------------
        int r0    = ib + wm + (lane >> 2);
        int cbase = wn + (lane & 3) * 2;
#pragma unroll
        for (int mf = 0; mf < 2; ++mf)
#pragma unroll
            for (int nf = 0; nf < 4; ++nf) {
                int row = r0 + mf * 16;
                int col = cbase + nf * 8;
                float* p = &g_part[split][(size_t)row * D + col];
                *(float2*)p           = make_float2(acc[mf][nf][0], acc[mf][nf][1]);
                *(float2*)(p + 8 * D) = make_float2(acc[mf][nf][2], acc[mf][nf][3]);
            }
    }
}

// ---------------- K4: combine partials + residual + ELU ---------------------
__global__ void k_out(float* __restrict__ out) {
    int g = blockIdx.x * blockDim.x + threadIdx.x;
    float4 v = ((const float4*)g_h)[g];
#pragma unroll
    for (int s = 0; s < SPLIT; ++s) {
        float4 p = __ldg((const float4*)g_part[s] + g);
        v.x += p.x; v.y += p.y; v.z += p.z; v.w += p.w;
    }
    float4 o;
    o.x = (v.x > 0.f) ? v.x : expm1f(v.x);
    o.y = (v.y > 0.f) ? v.y : expm1f(v.y);
    o.z = (v.z > 0.f) ? v.z : expm1f(v.z);
    o.w = (v.w > 0.f) ? v.w : expm1f(v.w);
    ((float4*)out)[g] = o;
}

// ---------------- launch ----------------------------------------------------
extern "C" void kernel_launch(void* const* d_in, const int* in_sizes, int n_in,
                              void* d_out, int out_size) {
    (void)in_sizes; (void)n_in; (void)out_size;
    const float* x   = (const float*)d_in[0];
    const float* W   = (const float*)d_in[1];
    const float* a   = (const float*)d_in[2];
    const int*   adj = (const int*)d_in[3];
    float*       out = (float*)d_out;

    cudaFuncSetAttribute(k_agg, cudaFuncAttributeMaxDynamicSharedMemorySize, SMEM_DYN);

    k_h    <<<N, 128>>>(x, W, a);
    k_stats<<<N / SROWS, 256>>>(adj);
    k_agg  <<<NCTA, 256, SMEM_DYN>>>();
    k_out  <<<(N * D) / 1024, 256>>>(out);
}